// round 12
// baseline (speedup 1.0000x reference)
#include <cuda_runtime.h>
#include <cuda_bf16.h>
#include <math.h>
#include <cstdint>

#define P_PIX 16384   // 128*128
#define NCH   384
#define NQKV  1152
#define HEADS 8
#define CH    48      // per-head channels
#define NWIN  64      // tokens per 8x8 window
#define CSPLIT 32     // cattn K splits
#define GK    384     // GEMM K (both gemms)
#define BK    32      // K chunk (cp.async stage)
#define NKC   (GK / BK)   // 12 chunks
#define A_STR 40      // smem row stride (bf16), 80B: conflict-free ldmatrix
#define A_SZB (128 * A_STR * 2)   // bytes per A array tile (128 rows)
#define B_SZB (256 * A_STR * 2)   // bytes per B array tile (256 rows)
#define STG_B (2 * A_SZB + 2 * B_SZB)   // stage bytes = 61440

typedef unsigned long long u64t;

__device__ __forceinline__ u64t dup_f32(float a) {
    u64t r; asm("mov.b64 %0, {%1, %1};" : "=l"(r) : "f"(a)); return r;
}
__device__ __forceinline__ void ffma2(u64t& acc, u64t a, u64t b) {
    asm("fma.rn.f32x2 %0, %1, %2, %0;" : "+l"(acc) : "l"(a), "l"(b));
}
__device__ __forceinline__ u64t pack2(float lo, float hi) {
    u64t r; asm("mov.b64 %0, {%1, %2};" : "=l"(r) : "f"(lo), "f"(hi)); return r;
}
__device__ __forceinline__ uint32_t smem_u32(const void* p) {
    uint32_t a;
    asm("{ .reg .u64 t; cvta.to.shared.u64 t, %1; cvt.u32.u64 %0, t; }" : "=r"(a) : "l"(p));
    return a;
}
__device__ __forceinline__ void ldsm_x4(uint32_t* r, uint32_t addr) {
    asm volatile("ldmatrix.sync.aligned.m8n8.x4.shared.b16 {%0,%1,%2,%3}, [%4];"
                 : "=r"(r[0]), "=r"(r[1]), "=r"(r[2]), "=r"(r[3]) : "r"(addr));
}
__device__ __forceinline__ void ldsm_x2(uint32_t* r, uint32_t addr) {
    asm volatile("ldmatrix.sync.aligned.m8n8.x2.shared.b16 {%0,%1}, [%2];"
                 : "=r"(r[0]), "=r"(r[1]) : "r"(addr));
}
__device__ __forceinline__ void mma_bf16(float* c, const uint32_t* a, const uint32_t* b) {
    asm volatile("mma.sync.aligned.m16n8k16.row.col.f32.bf16.bf16.f32 "
                 "{%0,%1,%2,%3}, {%4,%5,%6,%7}, {%8,%9}, {%0,%1,%2,%3};"
                 : "+f"(c[0]), "+f"(c[1]), "+f"(c[2]), "+f"(c[3])
                 : "r"(a[0]), "r"(a[1]), "r"(a[2]), "r"(a[3]), "r"(b[0]), "r"(b[1]));
}
__device__ __forceinline__ void cp_async16(uint32_t saddr, const void* g) {
    asm volatile("cp.async.cg.shared.global [%0], [%1], 16;" :: "r"(saddr), "l"(g));
}
#define CP_COMMIT() asm volatile("cp.async.commit_group;" ::: "memory")
#define CP_WAIT1()  asm volatile("cp.async.wait_group 1;" ::: "memory")
#define CP_WAIT0()  asm volatile("cp.async.wait_group 0;" ::: "memory")

// ---------------- scratch (device globals; no allocs allowed) ----------------
__device__ float g_qkv[2ll * NQKV * P_PIX];
__device__ float g_dw [2ll * NQKV * P_PIX];
__device__ float g_sum[2ll * NCH  * P_PIX];
__device__ float g_cpart[CSPLIT * 16 * CH * CH];
__device__ float g_cnp[CSPLIT * 16 * 96];      // per-split row sum-of-squares (48 q + 48 k)
__device__ float g_ccoef[16 * CH * CH];
__device__ __nv_bfloat16 g_xth[2ll * P_PIX * GK];
__device__ __nv_bfloat16 g_xtl[2ll * P_PIX * GK];
__device__ __nv_bfloat16 g_wqh[NQKV * NCH];
__device__ __nv_bfloat16 g_wql[NQKV * NCH];
__device__ __nv_bfloat16 g_wph[NCH * NCH];
__device__ __nv_bfloat16 g_wpl[NCH * NCH];

// ---------------- weight split fp32 -> bf16 hi/lo ----------------
__global__ __launch_bounds__(256) void convert_w(
    const float* __restrict__ W, __nv_bfloat16* __restrict__ Wh,
    __nv_bfloat16* __restrict__ Wl, int n)
{
    int i = blockIdx.x * 256 + threadIdx.x;
    if (i >= n) return;
    float v = W[i];
    __nv_bfloat16 hi = __float2bfloat16(v);
    Wh[i] = hi;
    Wl[i] = __float2bfloat16(v - __bfloat162float(hi));
}

// ------- transpose+split: X fp32 [b][K=384][16384] -> T bf16 [b][16384][384] --
__global__ __launch_bounds__(256) void transpose_split(
    const float* __restrict__ X, __nv_bfloat16* __restrict__ Th,
    __nv_bfloat16* __restrict__ Tl)
{
    __shared__ float s[32][33];
    const int b  = blockIdx.z;
    const int p0 = blockIdx.x * 32;
    const int k0 = blockIdx.y * 32;
    const int tid = threadIdx.x;
    const int tx = tid & 31, ty = tid >> 5;
    const float* Xb = X + ((size_t)b * GK + k0) * P_PIX + p0;
#pragma unroll
    for (int i = 0; i < 4; i++)
        s[ty + 8 * i][tx] = Xb[(size_t)(ty + 8 * i) * P_PIX + tx];
    __syncthreads();
    const int row = tid >> 3;
    const int kk = (tid & 7) * 4;
    __nv_bfloat16 hv[4], lv[4];
#pragma unroll
    for (int j = 0; j < 4; j++) {
        float v = s[kk + j][row];
        hv[j] = __float2bfloat16(v);
        lv[j] = __float2bfloat16(v - __bfloat162float(hv[j]));
    }
    size_t ob = ((size_t)b * P_PIX + p0 + row) * GK + k0 + kk;
    *reinterpret_cast<__nv_bfloat162*>(&Th[ob])     = *reinterpret_cast<__nv_bfloat162*>(&hv[0]);
    *reinterpret_cast<__nv_bfloat162*>(&Th[ob + 2]) = *reinterpret_cast<__nv_bfloat162*>(&hv[2]);
    *reinterpret_cast<__nv_bfloat162*>(&Tl[ob])     = *reinterpret_cast<__nv_bfloat162*>(&lv[0]);
    *reinterpret_cast<__nv_bfloat162*>(&Tl[ob + 2]) = *reinterpret_cast<__nv_bfloat162*>(&lv[2]);
}

// ------------- split-bf16 HMMA GEMM, cp.async double-buffered ---------------
// A = W (hi/lo [m][k]); B = X^T (hi/lo [p][k]).
// CTA tile 128(m) x 256(p), 8 warps (2x4), warp tile 64x64. 3-pass schedule.
__global__ __launch_bounds__(256, 1) void hmma_gemm(
    const __nv_bfloat16* __restrict__ Wh, const __nv_bfloat16* __restrict__ Wl,
    const __nv_bfloat16* __restrict__ Th, const __nv_bfloat16* __restrict__ Tl,
    float* __restrict__ Y, int M)
{
    extern __shared__ __nv_bfloat16 sm[];
    const uint32_t sm32 = smem_u32(sm);

    const int tid = threadIdx.x;
    const int wid = tid >> 5, lane = tid & 31;
    const int wr = wid >> 2;          // 0..1  (m: 64 rows)
    const int wc = wid & 3;           // 0..3  (p: 64 cols)
    const int b  = blockIdx.z;
    const int m0 = blockIdx.y * 128;
    const int p0 = blockIdx.x * 256;

    const __nv_bfloat16* gAh = Wh + (size_t)m0 * GK;
    const __nv_bfloat16* gAl = Wl + (size_t)m0 * GK;
    const __nv_bfloat16* gBh = Th + ((size_t)b * P_PIX + p0) * GK;
    const __nv_bfloat16* gBl = Tl + ((size_t)b * P_PIX + p0) * GK;

    float acc[4][8][4];
#pragma unroll
    for (int i = 0; i < 4; i++)
#pragma unroll
        for (int j = 0; j < 8; j++)
#pragma unroll
            for (int r = 0; r < 4; r++) acc[i][j][r] = 0.f;

    // stage layout: [Ah | Al | Bh | Bl]
    auto issue = [&](int chunk, int buf) {
        const int kb = chunk * BK;
        const uint32_t bufb = sm32 + (uint32_t)buf * STG_B;
        // A arrays: 128 rows, 512 uint4 each
#pragma unroll
        for (int i = 0; i < 2; i++) {
            int idx = tid + i * 256;             // 0..511
            int row = idx >> 2, c8 = (idx & 3) * 8;
            size_t go = (size_t)row * GK + kb + c8;
            uint32_t so = (uint32_t)(row * A_STR + c8) * 2;
            cp_async16(bufb + so, gAh + go);
            cp_async16(bufb + A_SZB + so, gAl + go);
        }
        // B arrays: 256 rows, 1024 uint4 each
#pragma unroll
        for (int i = 0; i < 4; i++) {
            int idx = tid + i * 256;             // 0..1023
            int row = idx >> 2, c8 = (idx & 3) * 8;
            size_t go = (size_t)row * GK + kb + c8;
            uint32_t so = (uint32_t)(row * A_STR + c8) * 2;
            cp_async16(bufb + 2 * A_SZB + so, gBh + go);
            cp_async16(bufb + 2 * A_SZB + B_SZB + so, gBl + go);
        }
        CP_COMMIT();
    };

    issue(0, 0);
    issue(1, 1);

    for (int c = 0; c < NKC; c++) {
        if (c + 1 < NKC) CP_WAIT1(); else CP_WAIT0();
        __syncthreads();
        const uint32_t bufb = sm32 + (uint32_t)(c & 1) * STG_B;
        const uint32_t sAh32 = bufb;
        const uint32_t sAl32 = bufb + A_SZB;
        const uint32_t sBh32 = bufb + 2 * A_SZB;
        const uint32_t sBl32 = bufb + 2 * A_SZB + B_SZB;

#pragma unroll
        for (int ks = 0; ks < BK / 16; ks++) {
            const int k0 = ks * 16;
            const int nrow = wc * 64 + (lane & 7);
            const int ncol = k0 + ((lane >> 3) & 1) * 8;
            const int arow = wr * 64 + (lane & 15);
            const int acol = k0 + (lane >> 4) * 8;

            uint32_t bH[8][2], aH[4][4];
#pragma unroll
            for (int nt = 0; nt < 8; nt++)
                ldsm_x2(bH[nt], sBh32 + (uint32_t)((nrow + nt * 8) * A_STR + ncol) * 2);
#pragma unroll
            for (int mt = 0; mt < 4; mt++)
                ldsm_x4(aH[mt], sAh32 + (uint32_t)((arow + mt * 16) * A_STR + acol) * 2);
            // pass 1: aH x bH  (32 independent chains)
#pragma unroll
            for (int mt = 0; mt < 4; mt++)
#pragma unroll
                for (int nt = 0; nt < 8; nt++)
                    mma_bf16(acc[mt][nt], aH[mt], bH[nt]);
            // pass 2: aH x bL
            {
                uint32_t bL[8][2];
#pragma unroll
                for (int nt = 0; nt < 8; nt++)
                    ldsm_x2(bL[nt], sBl32 + (uint32_t)((nrow + nt * 8) * A_STR + ncol) * 2);
#pragma unroll
                for (int mt = 0; mt < 4; mt++)
#pragma unroll
                    for (int nt = 0; nt < 8; nt++)
                        mma_bf16(acc[mt][nt], aH[mt], bL[nt]);
            }
            // pass 3: aL x bH
            {
                uint32_t aL[4][4];
#pragma unroll
                for (int mt = 0; mt < 4; mt++)
                    ldsm_x4(aL[mt], sAl32 + (uint32_t)((arow + mt * 16) * A_STR + acol) * 2);
#pragma unroll
                for (int mt = 0; mt < 4; mt++)
#pragma unroll
                    for (int nt = 0; nt < 8; nt++)
                        mma_bf16(acc[mt][nt], aL[mt], bH[nt]);
            }
        }
        __syncthreads();
        if (c + 2 < NKC) issue(c + 2, c & 1);
    }

    // epilogue
    const int tq = lane >> 2;
    const int tr4 = lane & 3;
#pragma unroll
    for (int mt = 0; mt < 4; mt++) {
#pragma unroll
        for (int nt = 0; nt < 8; nt++) {
            int m  = m0 + wr * 64 + mt * 16 + tq;
            int p  = p0 + wc * 64 + nt * 8 + tr4 * 2;
            float* y0 = &Y[((size_t)b * M + m) * P_PIX + p];
            *reinterpret_cast<float2*>(y0) = make_float2(acc[mt][nt][0], acc[mt][nt][1]);
            float* y1 = &Y[((size_t)b * M + m + 8) * P_PIX + p];
            *reinterpret_cast<float2*>(y1) = make_float2(acc[mt][nt][2], acc[mt][nt][3]);
        }
    }
}

// ---------------- depthwise 3x3, pad 1, 4 pixels/thread ----------------
__global__ __launch_bounds__(256) void dwconv_kernel(
    const float* __restrict__ in, const float* __restrict__ Wd, float* __restrict__ out)
{
    int gid = blockIdx.x * 256 + threadIdx.x;
    int grp = gid & 4095;
    int bc  = gid >> 12;
    int ch  = bc % NQKV;
    int x0 = (grp & 31) * 4, y = grp >> 5;
    const float* ip = in + (size_t)bc * P_PIX;
    const float* w  = Wd + ch * 9;
    float o0 = 0.f, o1 = 0.f, o2 = 0.f, o3 = 0.f;
#pragma unroll
    for (int dy = -1; dy <= 1; dy++) {
        int yy = y + dy;
        if ((unsigned)yy >= 128u) continue;
        const float* rp = ip + yy * 128;
        float v[6];
#pragma unroll
        for (int t = 0; t < 6; t++) {
            int xx = x0 - 1 + t;
            v[t] = ((unsigned)xx < 128u) ? rp[xx] : 0.f;
        }
#pragma unroll
        for (int dx = 0; dx < 3; dx++) {
            float wv = w[(dy + 1) * 3 + dx];
            o0 = fmaf(wv, v[dx + 0], o0);
            o1 = fmaf(wv, v[dx + 1], o1);
            o2 = fmaf(wv, v[dx + 2], o2);
            o3 = fmaf(wv, v[dx + 3], o3);
        }
    }
    *reinterpret_cast<float4*>(&out[(size_t)bc * P_PIX + y * 128 + x0]) =
        make_float4(o0, o1, o2, o3);
}

// ------ cattn raw dots + fused row sumsq, split-K partials ------------------
__global__ __launch_bounds__(256) void cattn_kernel(
    const float* __restrict__ dw, float* __restrict__ part, float* __restrict__ cnp)
{
    const int bh = blockIdx.y;
    const int b = bh >> 3, h = bh & 7;
    const int kbase = blockIdx.x * (P_PIX / CSPLIT);
    const float* qb = dw + ((size_t)b * NQKV + h * CH) * P_PIX;
    const float* kb = dw + ((size_t)b * NQKV + NCH + h * CH) * P_PIX;

    __shared__ float sq[CH][65];
    __shared__ float sk[CH][65];

    const int tid = threadIdx.x;
    const int ti = tid >> 4, tj = tid & 15;
    const int i0 = ti * 3, j0 = tj * 3;

    float acc[3][3];
#pragma unroll
    for (int r = 0; r < 3; r++)
#pragma unroll
        for (int c = 0; c < 3; c++) acc[r][c] = 0.f;
    float nrm = 0.f;

    for (int kc = 0; kc < P_PIX / CSPLIT; kc += 64) {
        const int kpos = kbase + kc;
        for (int e = tid; e < CH * 16; e += 256) {
            int r = e >> 4, c4 = (e & 15) * 4;
            float4 vq = *reinterpret_cast<const float4*>(&qb[(size_t)r * P_PIX + kpos + c4]);
            float4 vk = *reinterpret_cast<const float4*>(&kb[(size_t)r * P_PIX + kpos + c4]);
            sq[r][c4] = vq.x; sq[r][c4+1] = vq.y; sq[r][c4+2] = vq.z; sq[r][c4+3] = vq.w;
            sk[r][c4] = vk.x; sk[r][c4+1] = vk.y; sk[r][c4+2] = vk.z; sk[r][c4+3] = vk.w;
        }
        __syncthreads();
        if (tid < 96) {
            const float* rowp = (tid < 48) ? &sq[tid][0] : &sk[tid - 48][0];
#pragma unroll 16
            for (int c = 0; c < 64; c++) nrm = fmaf(rowp[c], rowp[c], nrm);
        }
#pragma unroll 8
        for (int kk = 0; kk < 64; kk++) {
            float a0 = sq[i0][kk], a1 = sq[i0+1][kk], a2 = sq[i0+2][kk];
            float b0 = sk[j0][kk], b1 = sk[j0+1][kk], b2 = sk[j0+2][kk];
            acc[0][0] = fmaf(a0, b0, acc[0][0]);
            acc[0][1] = fmaf(a0, b1, acc[0][1]);
            acc[0][2] = fmaf(a0, b2, acc[0][2]);
            acc[1][0] = fmaf(a1, b0, acc[1][0]);
            acc[1][1] = fmaf(a1, b1, acc[1][1]);
            acc[1][2] = fmaf(a1, b2, acc[1][2]);
            acc[2][0] = fmaf(a2, b0, acc[2][0]);
            acc[2][1] = fmaf(a2, b1, acc[2][1]);
            acc[2][2] = fmaf(a2, b2, acc[2][2]);
        }
        __syncthreads();
    }
    float* pr = &part[((size_t)blockIdx.x * 16 + bh) * (CH * CH)];
#pragma unroll
    for (int r = 0; r < 3; r++)
#pragma unroll
        for (int c = 0; c < 3; c++)
            pr[(i0 + r) * CH + (j0 + c)] = acc[r][c];
    if (tid < 96)
        cnp[((size_t)blockIdx.x * 16 + bh) * 96 + tid] = nrm;
}

// ------- channel branch: combined top-k softmax coefficients ----------------
__global__ __launch_bounds__(256) void chan_coef_kernel(
    const float* __restrict__ part, const float* __restrict__ cnp,
    const float* __restrict__ temp,
    const float* __restrict__ w1p, const float* __restrict__ w2p,
    const float* __restrict__ w3p, const float* __restrict__ w4p,
    float* __restrict__ coef)
{
    const int warp = threadIdx.x >> 5, ln = threadIdx.x & 31;
    const int row = blockIdx.x * 8 + warp;
    const int bh = row / CH, i = row % CH;
    const int h = bh & 7;
    const float t = temp[h];
    const int KT[4] = {23, 31, 35, 37};
    float wts[4] = {w1p[0], w2p[0], w3p[0], w4p[0]};

    __shared__ float sa[8][CH];
    __shared__ float sth[8][4];

    int j0 = ln, j1 = ln + 32;
    float d0 = 0.f, d1 = 0.f, sqi = 0.f, skk0 = 0.f, skk1 = 0.f;
    for (int s = 0; s < CSPLIT; s++) {
        const float* pr = part + ((size_t)s * 16 + bh) * (CH * CH) + i * CH;
        const float* np = cnp + ((size_t)s * 16 + bh) * 96;
        d0 += pr[j0];
        sqi += np[i];
        skk0 += np[48 + j0];
        if (j1 < CH) { d1 += pr[j1]; skk1 += np[48 + j1]; }
    }
    float inq = 1.f / fmaxf(sqrtf(sqi), 1e-12f);
    float nk0 = fmaxf(sqrtf(skk0), 1e-12f);
    float nk1 = fmaxf(sqrtf(skk1), 1e-12f);
    float a0 = d0 * inq / nk0 * t;
    float a1 = (j1 < CH) ? d1 * inq / nk1 * t : -INFINITY;
    sa[warp][j0] = a0;
    if (j1 < CH) sa[warp][j1] = a1;
    __syncwarp();

    int r0 = 0, r1 = 0;
    for (int q = 0; q < CH; q++) {
        float aq = sa[warp][q];
        r0 += (aq > a0) || (aq == a0 && q < j0);
        if (j1 < CH) r1 += (aq > a1) || (aq == a1 && q < j1);
    }
#pragma unroll
    for (int kx = 0; kx < 4; kx++) {
        if (r0 == KT[kx]) sth[warp][kx] = a0;
        if (j1 < CH && r1 == KT[kx]) sth[warp][kx] = a1;
    }
    __syncwarp();

    float m = fmaxf(a0, a1);
#pragma unroll
    for (int o = 16; o; o >>= 1) m = fmaxf(m, __shfl_xor_sync(0xffffffffu, m, o));
    float e0 = expf(a0 - m);
    float e1 = (j1 < CH) ? expf(a1 - m) : 0.f;

    float c0 = 0.f, c1 = 0.f;
#pragma unroll
    for (int kx = 0; kx < 4; kx++) {
        float th = sth[warp][kx];
        float zz = (a0 >= th ? e0 : 0.f) + ((j1 < CH && a1 >= th) ? e1 : 0.f);
#pragma unroll
        for (int o = 16; o; o >>= 1) zz += __shfl_xor_sync(0xffffffffu, zz, o);
        float f = wts[kx] / zz;
        if (a0 >= th) c0 += f;
        if (j1 < CH && a1 >= th) c1 += f;
    }
    coef[row * CH + j0] = e0 * c0;
    if (j1 < CH) coef[row * CH + j1] = e1 * c1;
}

// ------- cout = coef @ vc, packed i-pairs, broadcast shared loads -----------
__global__ __launch_bounds__(256) void cout_kernel(
    const float* __restrict__ coef, const float* __restrict__ dw,
    float* __restrict__ out)
{
    int bh = blockIdx.y; int b = bh >> 3, h = bh & 7;
    int p = blockIdx.x * 256 + threadIdx.x;
    __shared__ u64t scp[CH][CH / 2];
    const float* cf = coef + bh * CH * CH;
    for (int e = threadIdx.x; e < CH * (CH / 2); e += 256) {
        int j = e / (CH / 2), i2 = e % (CH / 2);
        scp[j][i2] = pack2(cf[(2 * i2) * CH + j], cf[(2 * i2 + 1) * CH + j]);
    }
    __syncthreads();
    const float* vb = dw + ((size_t)b * NQKV + 2 * NCH + h * CH) * P_PIX + p;
    u64t acc2[CH / 2];
#pragma unroll
    for (int i = 0; i < CH / 2; i++) acc2[i] = 0ull;
    for (int j = 0; j < CH; j++) {
        u64t vd = dup_f32(vb[(size_t)j * P_PIX]);
#pragma unroll
        for (int i = 0; i < CH / 2; i++) ffma2(acc2[i], vd, scp[j][i]);
    }
    float* ob = out + ((size_t)b * NCH + h * CH) * P_PIX + p;
#pragma unroll
    for (int i = 0; i < CH / 2; i++) {
        float lo, hi;
        asm("mov.b64 {%0, %1}, %2;" : "=f"(lo), "=f"(hi) : "l"(acc2[i]));
        ob[(size_t)(2 * i) * P_PIX]     = lo;
        ob[(size_t)(2 * i + 1) * P_PIX] = hi;
    }
}

// ------------- fused spatial window attention, register-tiled ----------------
#define SQ_STR 50
#define SAT_STR 66
__global__ __launch_bounds__(256) void spatial_kernel(
    const float* __restrict__ dw, const float* __restrict__ temp,
    const float* __restrict__ w1p, const float* __restrict__ w2p,
    const float* __restrict__ w3p, const float* __restrict__ w4p,
    float* __restrict__ out)
{
    extern __shared__ float smemf[];
    float* sq  = smemf;                      // 64*50 (later reused as obuf 48*66)
    float* sk2 = sq  + 64 * SQ_STR;          // 64*50
    float* svT = sk2 + 64 * SQ_STR;          // 48*66
    float* sat = svT + 48 * SAT_STR;         // 64*66
    float* nq  = sat + 64 * SAT_STR;         // 64
    float* nk  = nq  + 64;                   // 64
    float* sth = nk  + 64;                   // 64*4

    const int win = blockIdx.x;
    const int head = blockIdx.y;
    const int b = win >> 8, wy = (win >> 4) & 15, wx = win & 15;
    const int tid = threadIdx.x;
    const int ti = tid >> 4, tj = tid & 15;

    const size_t base = ((size_t)b * NQKV + head * CH) * P_PIX + (size_t)(wy * 8) * 128 + wx * 8;

    for (int e = tid; e < NWIN * CH; e += 256) {
        int c = e >> 6, n = e & 63;
        int iy = n >> 3, ix = n & 7;
        size_t off = (size_t)c * P_PIX + iy * 128 + ix;
        sq [n * SQ_STR + c] = dw[base + off];
        sk2[n * SQ_STR + c] = dw[base + (size_t)NCH * P_PIX + off];
        svT[c * SAT_STR + n] = dw[base + (size_t)(2 * NCH) * P_PIX + off];
    }
    __syncthreads();

    if (tid < 128) {
        int n = tid & 63;
        const float* src = (tid < 64) ? sq : sk2;
        float s = 0.f;
#pragma unroll
        for (int c = 0; c < CH; c++) { float v = src[n * SQ_STR + c]; s = fmaf(v, v, s); }
        float nn = fmaxf(sqrtf(s), 1e-12f);
        if (tid < 64) nq[n] = nn; else nk[n] = nn;
    }
    __syncthreads();

    const float t = temp[wx & 7];
    {
        float accq[4][4];
#pragma unroll
        for (int i = 0; i < 4; i++)
#pragma unroll
            for (int j = 0; j < 4; j++) accq[i][j] = 0.f;
        for (int c = 0; c < CH; c++) {
            float qv[4], kv[4];
#pragma unroll
            for (int i = 0; i < 4; i++) qv[i] = sq[(ti + 16 * i) * SQ_STR + c];
#pragma unroll
            for (int j = 0; j < 4; j++) kv[j] = sk2[(tj + 16 * j) * SQ_STR + c];
#pragma unroll
            for (int i = 0; i < 4; i++)
#pragma unroll
                for (int j = 0; j < 4; j++)
                    accq[i][j] = fmaf(qv[i], kv[j], accq[i][j]);
        }
        float qn[4], kn[4];
#pragma unroll
        for (int i = 0; i < 4; i++) qn[i] = nq[ti + 16 * i];
#pragma unroll
        for (int j = 0; j < 4; j++) kn[j] = nk[tj + 16 * j];
#pragma unroll
        for (int i = 0; i < 4; i++)
#pragma unroll
            for (int j = 0; j < 4; j++)
                sat[(ti + 16 * i) * SAT_STR + tj + 16 * j] = accq[i][j] / (qn[i] * kn[j]) * t;
    }
    __syncthreads();

    const int warp = tid >> 5, ln = tid & 31;
    const int KT[4] = {31, 41, 47, 50};
    float wts[4] = {w1p[0], w2p[0], w3p[0], w4p[0]};

    for (int rr = 0; rr < 8; rr++) {
        int n = warp * 8 + rr;
        float a0 = sat[n * SAT_STR + ln];
        float a1 = sat[n * SAT_STR + ln + 32];
        int r0 = 0, r1 = 0;
        for (int i2 = 0; i2 < NWIN; i2++) {
            float ai = sat[n * SAT_STR + i2];
            r0 += (ai > a0) || (ai == a0 && i2 < ln);
            r1 += (ai > a1) || (ai == a1 && i2 < ln + 32);
        }
#pragma unroll
        for (int kx = 0; kx < 4; kx++) {
            if (r0 == KT[kx]) sth[n * 4 + kx] = a0;
            if (r1 == KT[kx]) sth[n * 4 + kx] = a1;
        }
        __syncwarp();

        float m = fmaxf(a0, a1);
#pragma unroll
        for (int o = 16; o; o >>= 1) m = fmaxf(m, __shfl_xor_sync(0xffffffffu, m, o));
        float e0 = expf(a0 - m), e1 = expf(a1 - m);

        float c0 = 0.f, c1 = 0.f;
#pragma unroll
        for (int kx = 0; kx < 4; kx++) {
            float th = sth[n * 4 + kx];
            float zz = (a0 >= th ? e0 : 0.f) + (a1 >= th ? e1 : 0.f);
#pragma unroll
            for (int o = 16; o; o >>= 1) zz += __shfl_xor_sync(0xffffffffu, zz, o);
            float f = wts[kx] / zz;
            if (a0 >= th) c0 += f;
            if (a1 >= th) c1 += f;
        }
        __syncwarp();
        sat[n * SAT_STR + ln]      = e0 * c0;
        sat[n * SAT_STR + ln + 32] = e1 * c1;
        __syncwarp();
    }
    __syncthreads();

    {
        float acca[3][4];
#pragma unroll
        for (int i = 0; i < 3; i++)
#pragma unroll
            for (int j = 0; j < 4; j++) acca[i][j] = 0.f;
        for (int m = 0; m < NWIN; m++) {
            float av[4], vv[3];
#pragma unroll
            for (int j = 0; j < 4; j++) av[j] = sat[(ti + 16 * j) * SAT_STR + m];
#pragma unroll
            for (int i = 0; i < 3; i++) vv[i] = svT[(tj + 16 * i) * SAT_STR + m];
#pragma unroll
            for (int i = 0; i < 3; i++)
#pragma unroll
                for (int j = 0; j < 4; j++)
                    acca[i][j] = fmaf(av[j], vv[i], acca[i][j]);
        }
        float* obuf = sq;
#pragma unroll
        for (int i = 0; i < 3; i++)
#pragma unroll
            for (int j = 0; j < 4; j++)
                obuf[(tj + 16 * i) * SAT_STR + ti + 16 * j] = acca[i][j];
    }
    __syncthreads();

    {
        const float* obuf = sq;
#pragma unroll
        for (int o = 0; o < 12; o++) {
            int e = tid + o * 256;
            int c = e >> 6, n = e & 63;
            int p = wy * 1024 + wx * 64 + n;
            size_t oidx = ((size_t)b * NCH + head * CH + c) * P_PIX + p;
            out[oidx] += obuf[c * SAT_STR + n];
        }
    }
}

// ---------------- host launcher ----------------
extern "C" void kernel_launch(void* const* d_in, const int* in_sizes, int n_in,
                              void* d_out, int out_size)
{
    const float* x      = (const float*)d_in[0];
    const float* w_qkv  = (const float*)d_in[1];
    const float* w_dw   = (const float*)d_in[2];
    const float* w_proj = (const float*)d_in[3];
    const float* temp   = (const float*)d_in[4];
    const float* a1     = (const float*)d_in[5];
    const float* a2     = (const float*)d_in[6];
    const float* a3     = (const float*)d_in[7];
    const float* a4     = (const float*)d_in[8];
    float* out = (float*)d_out;

    float *qkv, *dwb, *sum, *cpart, *cnp, *ccoef;
    __nv_bfloat16 *xth, *xtl, *wqh, *wql, *wph, *wpl;
    cudaGetSymbolAddress((void**)&qkv,   g_qkv);
    cudaGetSymbolAddress((void**)&dwb,   g_dw);
    cudaGetSymbolAddress((void**)&sum,   g_sum);
    cudaGetSymbolAddress((void**)&cpart, g_cpart);
    cudaGetSymbolAddress((void**)&cnp,   g_cnp);
    cudaGetSymbolAddress((void**)&ccoef, g_ccoef);
    cudaGetSymbolAddress((void**)&xth,   g_xth);
    cudaGetSymbolAddress((void**)&xtl,   g_xtl);
    cudaGetSymbolAddress((void**)&wqh,   g_wqh);
    cudaGetSymbolAddress((void**)&wql,   g_wql);
    cudaGetSymbolAddress((void**)&wph,   g_wph);
    cudaGetSymbolAddress((void**)&wpl,   g_wpl);

    const int spatial_smem =
        (64 * SQ_STR * 2 + 48 * SAT_STR + 64 * SAT_STR + 64 + 64 + 64 * 4) * 4;
    const int gemm_smem = 2 * STG_B;   // 122880 B
    cudaFuncSetAttribute(spatial_kernel, cudaFuncAttributeMaxDynamicSharedMemorySize, 65536);
    cudaFuncSetAttribute(hmma_gemm, cudaFuncAttributeMaxDynamicSharedMemorySize, gemm_smem);

    // 0) weight splits + X transpose/split
    convert_w<<<(NQKV * NCH + 255) / 256, 256>>>(w_qkv, wqh, wql, NQKV * NCH);
    convert_w<<<(NCH * NCH + 255) / 256, 256>>>(w_proj, wph, wpl, NCH * NCH);
    transpose_split<<<dim3(P_PIX / 32, GK / 32, 2), 256>>>(x, xth, xtl);
    // 1) qkv = 1x1 conv via split-bf16 HMMA (M=1152), CTA tile 128x256
    hmma_gemm<<<dim3(P_PIX / 256, NQKV / 128, 2), 256, gemm_smem>>>(wqh, wql, xth, xtl, qkv, NQKV);
    // 2) depthwise 3x3
    dwconv_kernel<<<(2 * NQKV * P_PIX / 4) / 256, 256>>>(qkv, w_dw, dwb);
    // 3) cattn split-K partials + fused row norms
    cattn_kernel<<<dim3(CSPLIT, 16), 256>>>(dwb, cpart, cnp);
    // 4) channel softmax coefficients (reduces norms inline)
    chan_coef_kernel<<<96, 256>>>(cpart, cnp, temp, a1, a2, a3, a4, ccoef);
    // 5) cout = coef @ v
    cout_kernel<<<dim3(P_PIX / 256, 16), 256>>>(ccoef, dwb, sum);
    // 6) fused spatial window attention (adds into g_sum)
    spatial_kernel<<<dim3(512, HEADS), 256, spatial_smem>>>(dwb, temp, a1, a2, a3, a4, sum);
    // 7) proj: transpose/split g_sum, then HMMA GEMM (M=384) -> d_out
    transpose_split<<<dim3(P_PIX / 32, GK / 32, 2), 256>>>(sum, xth, xtl);
    hmma_gemm<<<dim3(P_PIX / 256, NCH / 128, 2), 256, gemm_smem>>>(wph, wpl, xth, xtl, out, NCH);
}

// round 13
// speedup vs baseline: 1.0448x; 1.0448x over previous
#include <cuda_runtime.h>
#include <cuda_bf16.h>
#include <math.h>
#include <cstdint>

#define P_PIX 16384   // 128*128
#define NCH   384
#define NQKV  1152
#define HEADS 8
#define CH    48      // per-head channels
#define NWIN  64      // tokens per 8x8 window
#define CSPLIT 32     // cattn K splits
#define GK    384     // GEMM K (both gemms)
#define BK    32      // K chunk (cp.async stage)
#define NKC   (GK / BK)   // 12 chunks
#define A_STR 40      // smem row stride (bf16), 80B: conflict-free ldmatrix
#define AS    (128 * A_STR)   // elems per array tile

typedef unsigned long long u64t;

__device__ __forceinline__ u64t dup_f32(float a) {
    u64t r; asm("mov.b64 %0, {%1, %1};" : "=l"(r) : "f"(a)); return r;
}
__device__ __forceinline__ void ffma2(u64t& acc, u64t a, u64t b) {
    asm("fma.rn.f32x2 %0, %1, %2, %0;" : "+l"(acc) : "l"(a), "l"(b));
}
__device__ __forceinline__ u64t pack2(float lo, float hi) {
    u64t r; asm("mov.b64 %0, {%1, %2};" : "=l"(r) : "f"(lo), "f"(hi)); return r;
}
__device__ __forceinline__ uint32_t smem_u32(const void* p) {
    uint32_t a;
    asm("{ .reg .u64 t; cvta.to.shared.u64 t, %1; cvt.u32.u64 %0, t; }" : "=r"(a) : "l"(p));
    return a;
}
__device__ __forceinline__ void ldsm_x4(uint32_t* r, uint32_t addr) {
    asm volatile("ldmatrix.sync.aligned.m8n8.x4.shared.b16 {%0,%1,%2,%3}, [%4];"
                 : "=r"(r[0]), "=r"(r[1]), "=r"(r[2]), "=r"(r[3]) : "r"(addr));
}
__device__ __forceinline__ void ldsm_x2(uint32_t* r, uint32_t addr) {
    asm volatile("ldmatrix.sync.aligned.m8n8.x2.shared.b16 {%0,%1}, [%2];"
                 : "=r"(r[0]), "=r"(r[1]) : "r"(addr));
}
__device__ __forceinline__ void mma_bf16(float* c, const uint32_t* a, const uint32_t* b) {
    asm volatile("mma.sync.aligned.m16n8k16.row.col.f32.bf16.bf16.f32 "
                 "{%0,%1,%2,%3}, {%4,%5,%6,%7}, {%8,%9}, {%0,%1,%2,%3};"
                 : "+f"(c[0]), "+f"(c[1]), "+f"(c[2]), "+f"(c[3])
                 : "r"(a[0]), "r"(a[1]), "r"(a[2]), "r"(a[3]), "r"(b[0]), "r"(b[1]));
}
__device__ __forceinline__ void cp_async16(uint32_t saddr, const void* g) {
    asm volatile("cp.async.cg.shared.global [%0], [%1], 16;" :: "r"(saddr), "l"(g));
}
#define CP_COMMIT() asm volatile("cp.async.commit_group;" ::: "memory")
#define CP_WAIT1()  asm volatile("cp.async.wait_group 1;" ::: "memory")
#define CP_WAIT0()  asm volatile("cp.async.wait_group 0;" ::: "memory")

// ---------------- scratch (device globals; no allocs allowed) ----------------
__device__ float g_qkv[2ll * NQKV * P_PIX];
__device__ float g_dw [2ll * NQKV * P_PIX];
__device__ float g_sum[2ll * NCH  * P_PIX];
__device__ float g_cpart[CSPLIT * 16 * CH * CH];
__device__ float g_cnp[CSPLIT * 16 * 96];      // per-split row sum-of-squares (48 q + 48 k)
__device__ float g_ccoef[16 * CH * CH];
__device__ __nv_bfloat16 g_xth[2ll * P_PIX * GK];
__device__ __nv_bfloat16 g_xtl[2ll * P_PIX * GK];
__device__ __nv_bfloat16 g_wqh[NQKV * NCH];
__device__ __nv_bfloat16 g_wql[NQKV * NCH];
__device__ __nv_bfloat16 g_wph[NCH * NCH];
__device__ __nv_bfloat16 g_wpl[NCH * NCH];

// ---------------- weight split fp32 -> bf16 hi/lo ----------------
__global__ __launch_bounds__(256) void convert_w(
    const float* __restrict__ W, __nv_bfloat16* __restrict__ Wh,
    __nv_bfloat16* __restrict__ Wl, int n)
{
    int i = blockIdx.x * 256 + threadIdx.x;
    if (i >= n) return;
    float v = W[i];
    __nv_bfloat16 hi = __float2bfloat16(v);
    Wh[i] = hi;
    Wl[i] = __float2bfloat16(v - __bfloat162float(hi));
}

// ------- transpose+split: X fp32 [b][K=384][16384] -> T bf16 [b][16384][384] --
__global__ __launch_bounds__(256) void transpose_split(
    const float* __restrict__ X, __nv_bfloat16* __restrict__ Th,
    __nv_bfloat16* __restrict__ Tl)
{
    __shared__ float s[32][33];
    const int b  = blockIdx.z;
    const int p0 = blockIdx.x * 32;
    const int k0 = blockIdx.y * 32;
    const int tid = threadIdx.x;
    const int tx = tid & 31, ty = tid >> 5;
    const float* Xb = X + ((size_t)b * GK + k0) * P_PIX + p0;
#pragma unroll
    for (int i = 0; i < 4; i++)
        s[ty + 8 * i][tx] = Xb[(size_t)(ty + 8 * i) * P_PIX + tx];
    __syncthreads();
    const int row = tid >> 3;
    const int kk = (tid & 7) * 4;
    __nv_bfloat16 hv[4], lv[4];
#pragma unroll
    for (int j = 0; j < 4; j++) {
        float v = s[kk + j][row];
        hv[j] = __float2bfloat16(v);
        lv[j] = __float2bfloat16(v - __bfloat162float(hv[j]));
    }
    size_t ob = ((size_t)b * P_PIX + p0 + row) * GK + k0 + kk;
    *reinterpret_cast<__nv_bfloat162*>(&Th[ob])     = *reinterpret_cast<__nv_bfloat162*>(&hv[0]);
    *reinterpret_cast<__nv_bfloat162*>(&Th[ob + 2]) = *reinterpret_cast<__nv_bfloat162*>(&hv[2]);
    *reinterpret_cast<__nv_bfloat162*>(&Tl[ob])     = *reinterpret_cast<__nv_bfloat162*>(&lv[0]);
    *reinterpret_cast<__nv_bfloat162*>(&Tl[ob + 2]) = *reinterpret_cast<__nv_bfloat162*>(&lv[2]);
}

// ------------- split-bf16 HMMA GEMM, cp.async double-buffered (R9 config) ----
// A = W (hi/lo [m][k]); B = X^T (hi/lo [p][k]). CTA 128x128, warp 64x32.
__global__ __launch_bounds__(256, 2) void hmma_gemm(
    const __nv_bfloat16* __restrict__ Wh, const __nv_bfloat16* __restrict__ Wl,
    const __nv_bfloat16* __restrict__ Th, const __nv_bfloat16* __restrict__ Tl,
    float* __restrict__ Y, int M)
{
    extern __shared__ __nv_bfloat16 sm[];
    const uint32_t sm32 = smem_u32(sm);

    const int tid = threadIdx.x;
    const int wid = tid >> 5, lane = tid & 31;
    const int wr = wid >> 2;          // 0..1
    const int wc = wid & 3;           // 0..3
    const int b  = blockIdx.z;
    const int m0 = blockIdx.y * 128;
    const int p0 = blockIdx.x * 128;

    const __nv_bfloat16* gA[4];
    gA[0] = Wh + (size_t)m0 * GK;
    gA[1] = Wl + (size_t)m0 * GK;
    gA[2] = Th + ((size_t)b * P_PIX + p0) * GK;
    gA[3] = Tl + ((size_t)b * P_PIX + p0) * GK;

    float acc[4][4][4];
#pragma unroll
    for (int i = 0; i < 4; i++)
#pragma unroll
        for (int j = 0; j < 4; j++)
#pragma unroll
            for (int r = 0; r < 4; r++) acc[i][j][r] = 0.f;

    auto issue = [&](int chunk, int buf) {
        const int kb = chunk * BK;
        const uint32_t bufb = sm32 + (uint32_t)buf * 4 * AS * 2;
#pragma unroll
        for (int i = 0; i < 2; i++) {
            int idx = tid + i * 256;             // 0..511
            int row = idx >> 2, c8 = (idx & 3) * 8;
            size_t go = (size_t)row * GK + kb + c8;
            uint32_t so = bufb + (uint32_t)(row * A_STR + c8) * 2;
#pragma unroll
            for (int a = 0; a < 4; a++)
                cp_async16(so + (uint32_t)a * AS * 2, gA[a] + go);
        }
        CP_COMMIT();
    };

    issue(0, 0);
    issue(1, 1);

    for (int c = 0; c < NKC; c++) {
        if (c + 1 < NKC) CP_WAIT1(); else CP_WAIT0();
        __syncthreads();
        const uint32_t bufb = sm32 + (uint32_t)(c & 1) * 4 * AS * 2;
        const uint32_t sAh32 = bufb;
        const uint32_t sAl32 = bufb + AS * 2;
        const uint32_t sBh32 = bufb + 2 * AS * 2;
        const uint32_t sBl32 = bufb + 3 * AS * 2;

#pragma unroll
        for (int ks = 0; ks < BK / 16; ks++) {
            const int k0 = ks * 16;
            const int nrow = wc * 32 + (lane & 7);
            const int ncol = k0 + ((lane >> 3) & 1) * 8;
            const int arow = wr * 64 + (lane & 15);
            const int acol = k0 + (lane >> 4) * 8;

            uint32_t bH[4][2], aH[4][4];
#pragma unroll
            for (int nt = 0; nt < 4; nt++)
                ldsm_x2(bH[nt], sBh32 + (uint32_t)((nrow + nt * 8) * A_STR + ncol) * 2);
#pragma unroll
            for (int mt = 0; mt < 4; mt++)
                ldsm_x4(aH[mt], sAh32 + (uint32_t)((arow + mt * 16) * A_STR + acol) * 2);
#pragma unroll
            for (int mt = 0; mt < 4; mt++)
#pragma unroll
                for (int nt = 0; nt < 4; nt++)
                    mma_bf16(acc[mt][nt], aH[mt], bH[nt]);
            uint32_t bL[4][2];
#pragma unroll
            for (int nt = 0; nt < 4; nt++)
                ldsm_x2(bL[nt], sBl32 + (uint32_t)((nrow + nt * 8) * A_STR + ncol) * 2);
#pragma unroll
            for (int mt = 0; mt < 4; mt++)
#pragma unroll
                for (int nt = 0; nt < 4; nt++)
                    mma_bf16(acc[mt][nt], aH[mt], bL[nt]);
            uint32_t aL[4][4];
#pragma unroll
            for (int mt = 0; mt < 4; mt++)
                ldsm_x4(aL[mt], sAl32 + (uint32_t)((arow + mt * 16) * A_STR + acol) * 2);
#pragma unroll
            for (int mt = 0; mt < 4; mt++)
#pragma unroll
                for (int nt = 0; nt < 4; nt++)
                    mma_bf16(acc[mt][nt], aL[mt], bH[nt]);
        }
        __syncthreads();
        if (c + 2 < NKC) issue(c + 2, c & 1);
    }

    // epilogue
    const int tq = lane >> 2;
    const int tr4 = lane & 3;
#pragma unroll
    for (int mt = 0; mt < 4; mt++) {
#pragma unroll
        for (int nt = 0; nt < 4; nt++) {
            int m  = m0 + wr * 64 + mt * 16 + tq;
            int p  = p0 + wc * 32 + nt * 8 + tr4 * 2;
            float* y0 = &Y[((size_t)b * M + m) * P_PIX + p];
            *reinterpret_cast<float2*>(y0) = make_float2(acc[mt][nt][0], acc[mt][nt][1]);
            float* y1 = &Y[((size_t)b * M + m + 8) * P_PIX + p];
            *reinterpret_cast<float2*>(y1) = make_float2(acc[mt][nt][2], acc[mt][nt][3]);
        }
    }
}

// ---------------- depthwise 3x3, pad 1, 2-tall x 4-wide per thread ----------
__global__ __launch_bounds__(256) void dwconv_kernel(
    const float* __restrict__ in, const float* __restrict__ Wd, float* __restrict__ out)
{
    int gid = blockIdx.x * 256 + threadIdx.x;      // 2*1152*2048
    int grp = gid & 2047;
    int bc  = gid >> 11;
    int ch  = bc % NQKV;
    int x0 = (grp & 31) * 4, y0 = (grp >> 5) * 2;
    const float* ip = in + (size_t)bc * P_PIX;
    const float* w  = Wd + ch * 9;
    float o0[4] = {0.f, 0.f, 0.f, 0.f};
    float o1[4] = {0.f, 0.f, 0.f, 0.f};
#pragma unroll
    for (int r = 0; r < 4; r++) {                  // input rows y0-1 .. y0+2
        int yy = y0 - 1 + r;
        if ((unsigned)yy >= 128u) continue;
        const float* rp = ip + yy * 128;
        float v[6];
#pragma unroll
        for (int t = 0; t < 6; t++) {
            int xx = x0 - 1 + t;
            v[t] = ((unsigned)xx < 128u) ? rp[xx] : 0.f;
        }
#pragma unroll
        for (int dx = 0; dx < 3; dx++) {
            if (r < 3) {
                float wv = w[r * 3 + dx];
#pragma unroll
                for (int i = 0; i < 4; i++) o0[i] = fmaf(wv, v[dx + i], o0[i]);
            }
            if (r >= 1) {
                float wv = w[(r - 1) * 3 + dx];
#pragma unroll
                for (int i = 0; i < 4; i++) o1[i] = fmaf(wv, v[dx + i], o1[i]);
            }
        }
    }
    float* ob = out + (size_t)bc * P_PIX + y0 * 128 + x0;
    *reinterpret_cast<float4*>(ob)       = make_float4(o0[0], o0[1], o0[2], o0[3]);
    *reinterpret_cast<float4*>(ob + 128) = make_float4(o1[0], o1[1], o1[2], o1[3]);
}

// ------ cattn raw dots + fused row sumsq, split-K partials ------------------
__global__ __launch_bounds__(256) void cattn_kernel(
    const float* __restrict__ dw, float* __restrict__ part, float* __restrict__ cnp)
{
    const int bh = blockIdx.y;
    const int b = bh >> 3, h = bh & 7;
    const int kbase = blockIdx.x * (P_PIX / CSPLIT);
    const float* qb = dw + ((size_t)b * NQKV + h * CH) * P_PIX;
    const float* kb = dw + ((size_t)b * NQKV + NCH + h * CH) * P_PIX;

    __shared__ float sq[CH][65];
    __shared__ float sk[CH][65];

    const int tid = threadIdx.x;
    const int ti = tid >> 4, tj = tid & 15;
    const int i0 = ti * 3, j0 = tj * 3;

    float acc[3][3];
#pragma unroll
    for (int r = 0; r < 3; r++)
#pragma unroll
        for (int c = 0; c < 3; c++) acc[r][c] = 0.f;
    float nrm = 0.f;

    for (int kc = 0; kc < P_PIX / CSPLIT; kc += 64) {
        const int kpos = kbase + kc;
        for (int e = tid; e < CH * 16; e += 256) {
            int r = e >> 4, c4 = (e & 15) * 4;
            float4 vq = *reinterpret_cast<const float4*>(&qb[(size_t)r * P_PIX + kpos + c4]);
            float4 vk = *reinterpret_cast<const float4*>(&kb[(size_t)r * P_PIX + kpos + c4]);
            sq[r][c4] = vq.x; sq[r][c4+1] = vq.y; sq[r][c4+2] = vq.z; sq[r][c4+3] = vq.w;
            sk[r][c4] = vk.x; sk[r][c4+1] = vk.y; sk[r][c4+2] = vk.z; sk[r][c4+3] = vk.w;
        }
        __syncthreads();
        if (tid < 96) {
            const float* rowp = (tid < 48) ? &sq[tid][0] : &sk[tid - 48][0];
#pragma unroll 16
            for (int c = 0; c < 64; c++) nrm = fmaf(rowp[c], rowp[c], nrm);
        }
#pragma unroll 8
        for (int kk = 0; kk < 64; kk++) {
            float a0 = sq[i0][kk], a1 = sq[i0+1][kk], a2 = sq[i0+2][kk];
            float b0 = sk[j0][kk], b1 = sk[j0+1][kk], b2 = sk[j0+2][kk];
            acc[0][0] = fmaf(a0, b0, acc[0][0]);
            acc[0][1] = fmaf(a0, b1, acc[0][1]);
            acc[0][2] = fmaf(a0, b2, acc[0][2]);
            acc[1][0] = fmaf(a1, b0, acc[1][0]);
            acc[1][1] = fmaf(a1, b1, acc[1][1]);
            acc[1][2] = fmaf(a1, b2, acc[1][2]);
            acc[2][0] = fmaf(a2, b0, acc[2][0]);
            acc[2][1] = fmaf(a2, b1, acc[2][1]);
            acc[2][2] = fmaf(a2, b2, acc[2][2]);
        }
        __syncthreads();
    }
    float* pr = &part[((size_t)blockIdx.x * 16 + bh) * (CH * CH)];
#pragma unroll
    for (int r = 0; r < 3; r++)
#pragma unroll
        for (int c = 0; c < 3; c++)
            pr[(i0 + r) * CH + (j0 + c)] = acc[r][c];
    if (tid < 96)
        cnp[((size_t)blockIdx.x * 16 + bh) * 96 + tid] = nrm;
}

// ------- channel branch: combined top-k softmax coefficients ----------------
__global__ __launch_bounds__(256) void chan_coef_kernel(
    const float* __restrict__ part, const float* __restrict__ cnp,
    const float* __restrict__ temp,
    const float* __restrict__ w1p, const float* __restrict__ w2p,
    const float* __restrict__ w3p, const float* __restrict__ w4p,
    float* __restrict__ coef)
{
    const int warp = threadIdx.x >> 5, ln = threadIdx.x & 31;
    const int row = blockIdx.x * 8 + warp;
    const int bh = row / CH, i = row % CH;
    const int h = bh & 7;
    const float t = temp[h];
    const int KT[4] = {23, 31, 35, 37};
    float wts[4] = {w1p[0], w2p[0], w3p[0], w4p[0]};

    __shared__ float sa[8][CH];
    __shared__ float sth[8][4];

    int j0 = ln, j1 = ln + 32;
    float d0 = 0.f, d1 = 0.f, sqi = 0.f, skk0 = 0.f, skk1 = 0.f;
    for (int s = 0; s < CSPLIT; s++) {
        const float* pr = part + ((size_t)s * 16 + bh) * (CH * CH) + i * CH;
        const float* np = cnp + ((size_t)s * 16 + bh) * 96;
        d0 += pr[j0];
        sqi += np[i];
        skk0 += np[48 + j0];
        if (j1 < CH) { d1 += pr[j1]; skk1 += np[48 + j1]; }
    }
    float inq = 1.f / fmaxf(sqrtf(sqi), 1e-12f);
    float nk0 = fmaxf(sqrtf(skk0), 1e-12f);
    float nk1 = fmaxf(sqrtf(skk1), 1e-12f);
    float a0 = d0 * inq / nk0 * t;
    float a1 = (j1 < CH) ? d1 * inq / nk1 * t : -INFINITY;
    sa[warp][j0] = a0;
    if (j1 < CH) sa[warp][j1] = a1;
    __syncwarp();

    int r0 = 0, r1 = 0;
    for (int q = 0; q < CH; q++) {
        float aq = sa[warp][q];
        r0 += (aq > a0) || (aq == a0 && q < j0);
        if (j1 < CH) r1 += (aq > a1) || (aq == a1 && q < j1);
    }
#pragma unroll
    for (int kx = 0; kx < 4; kx++) {
        if (r0 == KT[kx]) sth[warp][kx] = a0;
        if (j1 < CH && r1 == KT[kx]) sth[warp][kx] = a1;
    }
    __syncwarp();

    float m = fmaxf(a0, a1);
#pragma unroll
    for (int o = 16; o; o >>= 1) m = fmaxf(m, __shfl_xor_sync(0xffffffffu, m, o));
    float e0 = expf(a0 - m);
    float e1 = (j1 < CH) ? expf(a1 - m) : 0.f;

    float th4[4], z[4];
#pragma unroll
    for (int kx = 0; kx < 4; kx++) {
        th4[kx] = sth[warp][kx];
        z[kx] = (a0 >= th4[kx] ? e0 : 0.f) + ((j1 < CH && a1 >= th4[kx]) ? e1 : 0.f);
    }
#pragma unroll
    for (int o = 16; o; o >>= 1) {
        z[0] += __shfl_xor_sync(0xffffffffu, z[0], o);
        z[1] += __shfl_xor_sync(0xffffffffu, z[1], o);
        z[2] += __shfl_xor_sync(0xffffffffu, z[2], o);
        z[3] += __shfl_xor_sync(0xffffffffu, z[3], o);
    }
    float c0 = 0.f, c1 = 0.f;
#pragma unroll
    for (int kx = 0; kx < 4; kx++) {
        float f = wts[kx] / z[kx];
        if (a0 >= th4[kx]) c0 += f;
        if (j1 < CH && a1 >= th4[kx]) c1 += f;
    }
    coef[row * CH + j0] = e0 * c0;
    if (j1 < CH) coef[row * CH + j1] = e1 * c1;
}

// ------- cout = coef @ vc, packed i-pairs, broadcast shared loads -----------
__global__ __launch_bounds__(256) void cout_kernel(
    const float* __restrict__ coef, const float* __restrict__ dw,
    float* __restrict__ out)
{
    int bh = blockIdx.y; int b = bh >> 3, h = bh & 7;
    int p = blockIdx.x * 256 + threadIdx.x;
    __shared__ u64t scp[CH][CH / 2];
    const float* cf = coef + bh * CH * CH;
    for (int e = threadIdx.x; e < CH * (CH / 2); e += 256) {
        int j = e / (CH / 2), i2 = e % (CH / 2);
        scp[j][i2] = pack2(cf[(2 * i2) * CH + j], cf[(2 * i2 + 1) * CH + j]);
    }
    __syncthreads();
    const float* vb = dw + ((size_t)b * NQKV + 2 * NCH + h * CH) * P_PIX + p;
    u64t acc2[CH / 2];
#pragma unroll
    for (int i = 0; i < CH / 2; i++) acc2[i] = 0ull;
    for (int j = 0; j < CH; j++) {
        u64t vd = dup_f32(vb[(size_t)j * P_PIX]);
#pragma unroll
        for (int i = 0; i < CH / 2; i++) ffma2(acc2[i], vd, scp[j][i]);
    }
    float* ob = out + ((size_t)b * NCH + h * CH) * P_PIX + p;
#pragma unroll
    for (int i = 0; i < CH / 2; i++) {
        float lo, hi;
        asm("mov.b64 {%0, %1}, %2;" : "=f"(lo), "=f"(hi) : "l"(acc2[i]));
        ob[(size_t)(2 * i) * P_PIX]     = lo;
        ob[(size_t)(2 * i + 1) * P_PIX] = hi;
    }
}

// ------------- fused spatial window attention, register-tiled ----------------
#define SQ_STR 50
#define SAT_STR 66
__global__ __launch_bounds__(256) void spatial_kernel(
    const float* __restrict__ dw, const float* __restrict__ temp,
    const float* __restrict__ w1p, const float* __restrict__ w2p,
    const float* __restrict__ w3p, const float* __restrict__ w4p,
    float* __restrict__ out)
{
    extern __shared__ float smemf[];
    float* sq  = smemf;                      // 64*50 (later reused as obuf 48*66)
    float* sk2 = sq  + 64 * SQ_STR;          // 64*50
    float* svT = sk2 + 64 * SQ_STR;          // 48*66
    float* sat = svT + 48 * SAT_STR;         // 64*66
    float* nq  = sat + 64 * SAT_STR;         // 64
    float* nk  = nq  + 64;                   // 64
    float* sth = nk  + 64;                   // 64*4

    const int win = blockIdx.x;
    const int head = blockIdx.y;
    const int b = win >> 8, wy = (win >> 4) & 15, wx = win & 15;
    const int tid = threadIdx.x;
    const int ti = tid >> 4, tj = tid & 15;

    const size_t base = ((size_t)b * NQKV + head * CH) * P_PIX + (size_t)(wy * 8) * 128 + wx * 8;

    for (int e = tid; e < NWIN * CH; e += 256) {
        int c = e >> 6, n = e & 63;
        int iy = n >> 3, ix = n & 7;
        size_t off = (size_t)c * P_PIX + iy * 128 + ix;
        sq [n * SQ_STR + c] = dw[base + off];
        sk2[n * SQ_STR + c] = dw[base + (size_t)NCH * P_PIX + off];
        svT[c * SAT_STR + n] = dw[base + (size_t)(2 * NCH) * P_PIX + off];
    }
    __syncthreads();

    if (tid < 128) {
        int n = tid & 63;
        const float* src = (tid < 64) ? sq : sk2;
        float s = 0.f;
#pragma unroll
        for (int c = 0; c < CH; c++) { float v = src[n * SQ_STR + c]; s = fmaf(v, v, s); }
        float nn = fmaxf(sqrtf(s), 1e-12f);
        if (tid < 64) nq[n] = nn; else nk[n] = nn;
    }
    __syncthreads();

    const float t = temp[wx & 7];
    {
        float accq[4][4];
#pragma unroll
        for (int i = 0; i < 4; i++)
#pragma unroll
            for (int j = 0; j < 4; j++) accq[i][j] = 0.f;
        for (int c = 0; c < CH; c++) {
            float qv[4], kv[4];
#pragma unroll
            for (int i = 0; i < 4; i++) qv[i] = sq[(ti + 16 * i) * SQ_STR + c];
#pragma unroll
            for (int j = 0; j < 4; j++) kv[j] = sk2[(tj + 16 * j) * SQ_STR + c];
#pragma unroll
            for (int i = 0; i < 4; i++)
#pragma unroll
                for (int j = 0; j < 4; j++)
                    accq[i][j] = fmaf(qv[i], kv[j], accq[i][j]);
        }
        float qn[4], kn[4];
#pragma unroll
        for (int i = 0; i < 4; i++) qn[i] = nq[ti + 16 * i];
#pragma unroll
        for (int j = 0; j < 4; j++) kn[j] = nk[tj + 16 * j];
#pragma unroll
        for (int i = 0; i < 4; i++)
#pragma unroll
            for (int j = 0; j < 4; j++)
                sat[(ti + 16 * i) * SAT_STR + tj + 16 * j] = accq[i][j] / (qn[i] * kn[j]) * t;
    }
    __syncthreads();

    const int warp = tid >> 5, ln = tid & 31;
    const int KT[4] = {31, 41, 47, 50};
    float wts[4] = {w1p[0], w2p[0], w3p[0], w4p[0]};

    for (int rr = 0; rr < 8; rr++) {
        int n = warp * 8 + rr;
        float a0 = sat[n * SAT_STR + ln];
        float a1 = sat[n * SAT_STR + ln + 32];
        int r0 = 0, r1 = 0;
        for (int i2 = 0; i2 < NWIN; i2++) {
            float ai = sat[n * SAT_STR + i2];
            r0 += (ai > a0) || (ai == a0 && i2 < ln);
            r1 += (ai > a1) || (ai == a1 && i2 < ln + 32);
        }
#pragma unroll
        for (int kx = 0; kx < 4; kx++) {
            if (r0 == KT[kx]) sth[n * 4 + kx] = a0;
            if (r1 == KT[kx]) sth[n * 4 + kx] = a1;
        }
        __syncwarp();

        float m = fmaxf(a0, a1);
#pragma unroll
        for (int o = 16; o; o >>= 1) m = fmaxf(m, __shfl_xor_sync(0xffffffffu, m, o));
        float e0 = expf(a0 - m), e1 = expf(a1 - m);

        // 4 independent interleaved reductions (pipelined shfl chains)
        float th4[4], z[4];
#pragma unroll
        for (int kx = 0; kx < 4; kx++) {
            th4[kx] = sth[n * 4 + kx];
            z[kx] = (a0 >= th4[kx] ? e0 : 0.f) + (a1 >= th4[kx] ? e1 : 0.f);
        }
#pragma unroll
        for (int o = 16; o; o >>= 1) {
            z[0] += __shfl_xor_sync(0xffffffffu, z[0], o);
            z[1] += __shfl_xor_sync(0xffffffffu, z[1], o);
            z[2] += __shfl_xor_sync(0xffffffffu, z[2], o);
            z[3] += __shfl_xor_sync(0xffffffffu, z[3], o);
        }
        float c0 = 0.f, c1 = 0.f;
#pragma unroll
        for (int kx = 0; kx < 4; kx++) {
            float f = wts[kx] / z[kx];
            if (a0 >= th4[kx]) c0 += f;
            if (a1 >= th4[kx]) c1 += f;
        }
        __syncwarp();
        sat[n * SAT_STR + ln]      = e0 * c0;
        sat[n * SAT_STR + ln + 32] = e1 * c1;
        __syncwarp();
    }
    __syncthreads();

    {
        float acca[3][4];
#pragma unroll
        for (int i = 0; i < 3; i++)
#pragma unroll
            for (int j = 0; j < 4; j++) acca[i][j] = 0.f;
        for (int m = 0; m < NWIN; m++) {
            float av[4], vv[3];
#pragma unroll
            for (int j = 0; j < 4; j++) av[j] = sat[(ti + 16 * j) * SAT_STR + m];
#pragma unroll
            for (int i = 0; i < 3; i++) vv[i] = svT[(tj + 16 * i) * SAT_STR + m];
#pragma unroll
            for (int i = 0; i < 3; i++)
#pragma unroll
                for (int j = 0; j < 4; j++)
                    acca[i][j] = fmaf(av[j], vv[i], acca[i][j]);
        }
        float* obuf = sq;
#pragma unroll
        for (int i = 0; i < 3; i++)
#pragma unroll
            for (int j = 0; j < 4; j++)
                obuf[(tj + 16 * i) * SAT_STR + ti + 16 * j] = acca[i][j];
    }
    __syncthreads();

    {
        const float* obuf = sq;
#pragma unroll
        for (int o = 0; o < 12; o++) {
            int e = tid + o * 256;
            int c = e >> 6, n = e & 63;
            int p = wy * 1024 + wx * 64 + n;
            size_t oidx = ((size_t)b * NCH + head * CH + c) * P_PIX + p;
            out[oidx] += obuf[c * SAT_STR + n];
        }
    }
}

// ---------------- host launcher ----------------
extern "C" void kernel_launch(void* const* d_in, const int* in_sizes, int n_in,
                              void* d_out, int out_size)
{
    const float* x      = (const float*)d_in[0];
    const float* w_qkv  = (const float*)d_in[1];
    const float* w_dw   = (const float*)d_in[2];
    const float* w_proj = (const float*)d_in[3];
    const float* temp   = (const float*)d_in[4];
    const float* a1     = (const float*)d_in[5];
    const float* a2     = (const float*)d_in[6];
    const float* a3     = (const float*)d_in[7];
    const float* a4     = (const float*)d_in[8];
    float* out = (float*)d_out;

    float *qkv, *dwb, *sum, *cpart, *cnp, *ccoef;
    __nv_bfloat16 *xth, *xtl, *wqh, *wql, *wph, *wpl;
    cudaGetSymbolAddress((void**)&qkv,   g_qkv);
    cudaGetSymbolAddress((void**)&dwb,   g_dw);
    cudaGetSymbolAddress((void**)&sum,   g_sum);
    cudaGetSymbolAddress((void**)&cpart, g_cpart);
    cudaGetSymbolAddress((void**)&cnp,   g_cnp);
    cudaGetSymbolAddress((void**)&ccoef, g_ccoef);
    cudaGetSymbolAddress((void**)&xth,   g_xth);
    cudaGetSymbolAddress((void**)&xtl,   g_xtl);
    cudaGetSymbolAddress((void**)&wqh,   g_wqh);
    cudaGetSymbolAddress((void**)&wql,   g_wql);
    cudaGetSymbolAddress((void**)&wph,   g_wph);
    cudaGetSymbolAddress((void**)&wpl,   g_wpl);

    const int spatial_smem =
        (64 * SQ_STR * 2 + 48 * SAT_STR + 64 * SAT_STR + 64 + 64 + 64 * 4) * 4;
    const int gemm_smem = 2 * 4 * AS * 2;   // 81920 B
    cudaFuncSetAttribute(spatial_kernel, cudaFuncAttributeMaxDynamicSharedMemorySize, 65536);
    cudaFuncSetAttribute(hmma_gemm, cudaFuncAttributeMaxDynamicSharedMemorySize, gemm_smem);

    // 0) weight splits + X transpose/split
    convert_w<<<(NQKV * NCH + 255) / 256, 256>>>(w_qkv, wqh, wql, NQKV * NCH);
    convert_w<<<(NCH * NCH + 255) / 256, 256>>>(w_proj, wph, wpl, NCH * NCH);
    transpose_split<<<dim3(P_PIX / 32, GK / 32, 2), 256>>>(x, xth, xtl);
    // 1) qkv = 1x1 conv via split-bf16 HMMA (M=1152)
    hmma_gemm<<<dim3(P_PIX / 128, NQKV / 128, 2), 256, gemm_smem>>>(wqh, wql, xth, xtl, qkv, NQKV);
    // 2) depthwise 3x3 (2x4 tile per thread)
    dwconv_kernel<<<(2 * NQKV * P_PIX / 8) / 256, 256>>>(qkv, w_dw, dwb);
    // 3) cattn split-K partials + fused row norms
    cattn_kernel<<<dim3(CSPLIT, 16), 256>>>(dwb, cpart, cnp);
    // 4) channel softmax coefficients (reduces norms inline)
    chan_coef_kernel<<<96, 256>>>(cpart, cnp, temp, a1, a2, a3, a4, ccoef);
    // 5) cout = coef @ v
    cout_kernel<<<dim3(P_PIX / 256, 16), 256>>>(ccoef, dwb, sum);
    // 6) fused spatial window attention (adds into g_sum)
    spatial_kernel<<<dim3(512, HEADS), 256, spatial_smem>>>(dwb, temp, a1, a2, a3, a4, sum);
    // 7) proj: transpose/split g_sum, then HMMA GEMM (M=384) -> d_out
    transpose_split<<<dim3(P_PIX / 32, GK / 32, 2), 256>>>(sum, xth, xtl);
    hmma_gemm<<<dim3(P_PIX / 128, NCH / 128, 2), 256, gemm_smem>>>(wph, wpl, xth, xtl, out, NCH);
}

// round 14
// speedup vs baseline: 1.0941x; 1.0472x over previous
#include <cuda_runtime.h>
#include <cuda_bf16.h>
#include <math.h>
#include <cstdint>

#define P_PIX 16384   // 128*128
#define NCH   384
#define NQKV  1152
#define HEADS 8
#define CH    48      // per-head channels
#define NWIN  64      // tokens per 8x8 window
#define CSPLIT 32     // cattn K splits
#define GK    384     // GEMM K (both gemms)
#define BK    32      // K chunk (cp.async stage)
#define NKC   (GK / BK)   // 12 chunks
#define A_STR 40      // smem row stride (bf16), 80B: conflict-free ldmatrix
#define AS    (128 * A_STR)   // elems per array tile

typedef unsigned long long u64t;

__device__ __forceinline__ u64t dup_f32(float a) {
    u64t r; asm("mov.b64 %0, {%1, %1};" : "=l"(r) : "f"(a)); return r;
}
__device__ __forceinline__ void ffma2(u64t& acc, u64t a, u64t b) {
    asm("fma.rn.f32x2 %0, %1, %2, %0;" : "+l"(acc) : "l"(a), "l"(b));
}
__device__ __forceinline__ float pair_sum(u64t v) {
    float lo, hi; asm("mov.b64 {%0, %1}, %2;" : "=f"(lo), "=f"(hi) : "l"(v)); return lo + hi;
}
__device__ __forceinline__ u64t pack2(float lo, float hi) {
    u64t r; asm("mov.b64 %0, {%1, %2};" : "=l"(r) : "f"(lo), "f"(hi)); return r;
}
__device__ __forceinline__ uint32_t smem_u32(const void* p) {
    uint32_t a;
    asm("{ .reg .u64 t; cvta.to.shared.u64 t, %1; cvt.u32.u64 %0, t; }" : "=r"(a) : "l"(p));
    return a;
}
__device__ __forceinline__ void ldsm_x4(uint32_t* r, uint32_t addr) {
    asm volatile("ldmatrix.sync.aligned.m8n8.x4.shared.b16 {%0,%1,%2,%3}, [%4];"
                 : "=r"(r[0]), "=r"(r[1]), "=r"(r[2]), "=r"(r[3]) : "r"(addr));
}
__device__ __forceinline__ void ldsm_x2(uint32_t* r, uint32_t addr) {
    asm volatile("ldmatrix.sync.aligned.m8n8.x2.shared.b16 {%0,%1}, [%2];"
                 : "=r"(r[0]), "=r"(r[1]) : "r"(addr));
}
__device__ __forceinline__ void mma_bf16(float* c, const uint32_t* a, const uint32_t* b) {
    asm volatile("mma.sync.aligned.m16n8k16.row.col.f32.bf16.bf16.f32 "
                 "{%0,%1,%2,%3}, {%4,%5,%6,%7}, {%8,%9}, {%0,%1,%2,%3};"
                 : "+f"(c[0]), "+f"(c[1]), "+f"(c[2]), "+f"(c[3])
                 : "r"(a[0]), "r"(a[1]), "r"(a[2]), "r"(a[3]), "r"(b[0]), "r"(b[1]));
}
__device__ __forceinline__ void cp_async16(uint32_t saddr, const void* g) {
    asm volatile("cp.async.cg.shared.global [%0], [%1], 16;" :: "r"(saddr), "l"(g));
}
#define CP_COMMIT() asm volatile("cp.async.commit_group;" ::: "memory")
#define CP_WAIT1()  asm volatile("cp.async.wait_group 1;" ::: "memory")
#define CP_WAIT0()  asm volatile("cp.async.wait_group 0;" ::: "memory")

// ---------------- scratch (device globals; no allocs allowed) ----------------
__device__ float g_qkv[2ll * NQKV * P_PIX];
__device__ float g_dw [2ll * NQKV * P_PIX];
__device__ float g_sum[2ll * NCH  * P_PIX];
__device__ float g_cpart[CSPLIT * 16 * CH * CH];
__device__ float g_cnp[CSPLIT * 16 * 96];      // per-split row sum-of-squares (48 q + 48 k)
__device__ float g_ccoef[16 * CH * CH];
__device__ __nv_bfloat16 g_xth[2ll * P_PIX * GK];
__device__ __nv_bfloat16 g_xtl[2ll * P_PIX * GK];
__device__ __nv_bfloat16 g_wqh[NQKV * NCH];
__device__ __nv_bfloat16 g_wql[NQKV * NCH];
__device__ __nv_bfloat16 g_wph[NCH * NCH];
__device__ __nv_bfloat16 g_wpl[NCH * NCH];

// ---------------- weight split fp32 -> bf16 hi/lo ----------------
__global__ __launch_bounds__(256) void convert_w(
    const float* __restrict__ W, __nv_bfloat16* __restrict__ Wh,
    __nv_bfloat16* __restrict__ Wl, int n)
{
    int i = blockIdx.x * 256 + threadIdx.x;
    if (i >= n) return;
    float v = W[i];
    __nv_bfloat16 hi = __float2bfloat16(v);
    Wh[i] = hi;
    Wl[i] = __float2bfloat16(v - __bfloat162float(hi));
}

// ------- transpose+split: X fp32 [b][K=384][16384] -> T bf16 [b][16384][384] --
__global__ __launch_bounds__(256) void transpose_split(
    const float* __restrict__ X, __nv_bfloat16* __restrict__ Th,
    __nv_bfloat16* __restrict__ Tl)
{
    __shared__ float s[32][33];
    const int b  = blockIdx.z;
    const int p0 = blockIdx.x * 32;
    const int k0 = blockIdx.y * 32;
    const int tid = threadIdx.x;
    const int tx = tid & 31, ty = tid >> 5;
    const float* Xb = X + ((size_t)b * GK + k0) * P_PIX + p0;
#pragma unroll
    for (int i = 0; i < 4; i++)
        s[ty + 8 * i][tx] = Xb[(size_t)(ty + 8 * i) * P_PIX + tx];
    __syncthreads();
    const int row = tid >> 3;
    const int kk = (tid & 7) * 4;
    __nv_bfloat16 hv[4], lv[4];
#pragma unroll
    for (int j = 0; j < 4; j++) {
        float v = s[kk + j][row];
        hv[j] = __float2bfloat16(v);
        lv[j] = __float2bfloat16(v - __bfloat162float(hv[j]));
    }
    size_t ob = ((size_t)b * P_PIX + p0 + row) * GK + k0 + kk;
    *reinterpret_cast<__nv_bfloat162*>(&Th[ob])     = *reinterpret_cast<__nv_bfloat162*>(&hv[0]);
    *reinterpret_cast<__nv_bfloat162*>(&Th[ob + 2]) = *reinterpret_cast<__nv_bfloat162*>(&hv[2]);
    *reinterpret_cast<__nv_bfloat162*>(&Tl[ob])     = *reinterpret_cast<__nv_bfloat162*>(&lv[0]);
    *reinterpret_cast<__nv_bfloat162*>(&Tl[ob + 2]) = *reinterpret_cast<__nv_bfloat162*>(&lv[2]);
}

// ------------- split-bf16 HMMA GEMM, cp.async double-buffered (R9 config) ----
__global__ __launch_bounds__(256, 2) void hmma_gemm(
    const __nv_bfloat16* __restrict__ Wh, const __nv_bfloat16* __restrict__ Wl,
    const __nv_bfloat16* __restrict__ Th, const __nv_bfloat16* __restrict__ Tl,
    float* __restrict__ Y, int M)
{
    extern __shared__ __nv_bfloat16 sm[];
    const uint32_t sm32 = smem_u32(sm);

    const int tid = threadIdx.x;
    const int wid = tid >> 5, lane = tid & 31;
    const int wr = wid >> 2;          // 0..1
    const int wc = wid & 3;           // 0..3
    const int b  = blockIdx.z;
    const int m0 = blockIdx.y * 128;
    const int p0 = blockIdx.x * 128;

    const __nv_bfloat16* gA[4];
    gA[0] = Wh + (size_t)m0 * GK;
    gA[1] = Wl + (size_t)m0 * GK;
    gA[2] = Th + ((size_t)b * P_PIX + p0) * GK;
    gA[3] = Tl + ((size_t)b * P_PIX + p0) * GK;

    float acc[4][4][4];
#pragma unroll
    for (int i = 0; i < 4; i++)
#pragma unroll
        for (int j = 0; j < 4; j++)
#pragma unroll
            for (int r = 0; r < 4; r++) acc[i][j][r] = 0.f;

    auto issue = [&](int chunk, int buf) {
        const int kb = chunk * BK;
        const uint32_t bufb = sm32 + (uint32_t)buf * 4 * AS * 2;
#pragma unroll
        for (int i = 0; i < 2; i++) {
            int idx = tid + i * 256;             // 0..511
            int row = idx >> 2, c8 = (idx & 3) * 8;
            size_t go = (size_t)row * GK + kb + c8;
            uint32_t so = bufb + (uint32_t)(row * A_STR + c8) * 2;
#pragma unroll
            for (int a = 0; a < 4; a++)
                cp_async16(so + (uint32_t)a * AS * 2, gA[a] + go);
        }
        CP_COMMIT();
    };

    issue(0, 0);
    issue(1, 1);

    for (int c = 0; c < NKC; c++) {
        if (c + 1 < NKC) CP_WAIT1(); else CP_WAIT0();
        __syncthreads();
        const uint32_t bufb = sm32 + (uint32_t)(c & 1) * 4 * AS * 2;
        const uint32_t sAh32 = bufb;
        const uint32_t sAl32 = bufb + AS * 2;
        const uint32_t sBh32 = bufb + 2 * AS * 2;
        const uint32_t sBl32 = bufb + 3 * AS * 2;

#pragma unroll
        for (int ks = 0; ks < BK / 16; ks++) {
            const int k0 = ks * 16;
            const int nrow = wc * 32 + (lane & 7);
            const int ncol = k0 + ((lane >> 3) & 1) * 8;
            const int arow = wr * 64 + (lane & 15);
            const int acol = k0 + (lane >> 4) * 8;

            uint32_t bH[4][2], aH[4][4];
#pragma unroll
            for (int nt = 0; nt < 4; nt++)
                ldsm_x2(bH[nt], sBh32 + (uint32_t)((nrow + nt * 8) * A_STR + ncol) * 2);
#pragma unroll
            for (int mt = 0; mt < 4; mt++)
                ldsm_x4(aH[mt], sAh32 + (uint32_t)((arow + mt * 16) * A_STR + acol) * 2);
#pragma unroll
            for (int mt = 0; mt < 4; mt++)
#pragma unroll
                for (int nt = 0; nt < 4; nt++)
                    mma_bf16(acc[mt][nt], aH[mt], bH[nt]);
            uint32_t bL[4][2];
#pragma unroll
            for (int nt = 0; nt < 4; nt++)
                ldsm_x2(bL[nt], sBl32 + (uint32_t)((nrow + nt * 8) * A_STR + ncol) * 2);
#pragma unroll
            for (int mt = 0; mt < 4; mt++)
#pragma unroll
                for (int nt = 0; nt < 4; nt++)
                    mma_bf16(acc[mt][nt], aH[mt], bL[nt]);
            uint32_t aL[4][4];
#pragma unroll
            for (int mt = 0; mt < 4; mt++)
                ldsm_x4(aL[mt], sAl32 + (uint32_t)((arow + mt * 16) * A_STR + acol) * 2);
#pragma unroll
            for (int mt = 0; mt < 4; mt++)
#pragma unroll
                for (int nt = 0; nt < 4; nt++)
                    mma_bf16(acc[mt][nt], aL[mt], bH[nt]);
        }
        __syncthreads();
        if (c + 2 < NKC) issue(c + 2, c & 1);
    }

    // epilogue
    const int tq = lane >> 2;
    const int tr4 = lane & 3;
#pragma unroll
    for (int mt = 0; mt < 4; mt++) {
#pragma unroll
        for (int nt = 0; nt < 4; nt++) {
            int m  = m0 + wr * 64 + mt * 16 + tq;
            int p  = p0 + wc * 32 + nt * 8 + tr4 * 2;
            float* y0 = &Y[((size_t)b * M + m) * P_PIX + p];
            *reinterpret_cast<float2*>(y0) = make_float2(acc[mt][nt][0], acc[mt][nt][1]);
            float* y1 = &Y[((size_t)b * M + m + 8) * P_PIX + p];
            *reinterpret_cast<float2*>(y1) = make_float2(acc[mt][nt][2], acc[mt][nt][3]);
        }
    }
}

// ---------------- depthwise 3x3, pad 1, 2-tall x 4-wide per thread ----------
__global__ __launch_bounds__(256) void dwconv_kernel(
    const float* __restrict__ in, const float* __restrict__ Wd, float* __restrict__ out)
{
    int gid = blockIdx.x * 256 + threadIdx.x;      // 2*1152*2048
    int grp = gid & 2047;
    int bc  = gid >> 11;
    int ch  = bc % NQKV;
    int x0 = (grp & 31) * 4, y0 = (grp >> 5) * 2;
    const float* ip = in + (size_t)bc * P_PIX;
    const float* w  = Wd + ch * 9;
    float o0[4] = {0.f, 0.f, 0.f, 0.f};
    float o1[4] = {0.f, 0.f, 0.f, 0.f};
#pragma unroll
    for (int r = 0; r < 4; r++) {                  // input rows y0-1 .. y0+2
        int yy = y0 - 1 + r;
        if ((unsigned)yy >= 128u) continue;
        const float* rp = ip + yy * 128;
        float v[6];
#pragma unroll
        for (int t = 0; t < 6; t++) {
            int xx = x0 - 1 + t;
            v[t] = ((unsigned)xx < 128u) ? rp[xx] : 0.f;
        }
#pragma unroll
        for (int dx = 0; dx < 3; dx++) {
            if (r < 3) {
                float wv = w[r * 3 + dx];
#pragma unroll
                for (int i = 0; i < 4; i++) o0[i] = fmaf(wv, v[dx + i], o0[i]);
            }
            if (r >= 1) {
                float wv = w[(r - 1) * 3 + dx];
#pragma unroll
                for (int i = 0; i < 4; i++) o1[i] = fmaf(wv, v[dx + i], o1[i]);
            }
        }
    }
    float* ob = out + (size_t)bc * P_PIX + y0 * 128 + x0;
    *reinterpret_cast<float4*>(ob)       = make_float4(o0[0], o0[1], o0[2], o0[3]);
    *reinterpret_cast<float4*>(ob + 128) = make_float4(o1[0], o1[1], o1[2], o1[3]);
}

// ------ cattn raw dots + fused row sumsq, split-K partials, f32x2 -----------
__global__ __launch_bounds__(256) void cattn_kernel(
    const float* __restrict__ dw, float* __restrict__ part, float* __restrict__ cnp)
{
    const int bh = blockIdx.y;
    const int b = bh >> 3, h = bh & 7;
    const int kbase = blockIdx.x * (P_PIX / CSPLIT);
    const float* qb = dw + ((size_t)b * NQKV + h * CH) * P_PIX;
    const float* kb = dw + ((size_t)b * NQKV + NCH + h * CH) * P_PIX;

    __shared__ float sq[CH][66];   // even stride: 8B-aligned rows for LDS.64
    __shared__ float sk[CH][66];

    const int tid = threadIdx.x;
    const int ti = tid >> 4, tj = tid & 15;
    const int i0 = ti * 3, j0 = tj * 3;

    u64t acc2[3][3];
#pragma unroll
    for (int r = 0; r < 3; r++)
#pragma unroll
        for (int c = 0; c < 3; c++) acc2[r][c] = 0ull;
    float nrm = 0.f;

    for (int kc = 0; kc < P_PIX / CSPLIT; kc += 64) {
        const int kpos = kbase + kc;
        for (int e = tid; e < CH * 16; e += 256) {
            int r = e >> 4, c4 = (e & 15) * 4;
            float4 vq = *reinterpret_cast<const float4*>(&qb[(size_t)r * P_PIX + kpos + c4]);
            float4 vk = *reinterpret_cast<const float4*>(&kb[(size_t)r * P_PIX + kpos + c4]);
            sq[r][c4] = vq.x; sq[r][c4+1] = vq.y; sq[r][c4+2] = vq.z; sq[r][c4+3] = vq.w;
            sk[r][c4] = vk.x; sk[r][c4+1] = vk.y; sk[r][c4+2] = vk.z; sk[r][c4+3] = vk.w;
        }
        __syncthreads();
        if (tid < 96) {
            const float* rowp = (tid < 48) ? &sq[tid][0] : &sk[tid - 48][0];
#pragma unroll 16
            for (int c = 0; c < 64; c++) nrm = fmaf(rowp[c], rowp[c], nrm);
        }
        const u64t* a0p = reinterpret_cast<const u64t*>(&sq[i0][0]);
        const u64t* a1p = reinterpret_cast<const u64t*>(&sq[i0 + 1][0]);
        const u64t* a2p = reinterpret_cast<const u64t*>(&sq[i0 + 2][0]);
        const u64t* b0p = reinterpret_cast<const u64t*>(&sk[j0][0]);
        const u64t* b1p = reinterpret_cast<const u64t*>(&sk[j0 + 1][0]);
        const u64t* b2p = reinterpret_cast<const u64t*>(&sk[j0 + 2][0]);
#pragma unroll 8
        for (int kk = 0; kk < 32; kk++) {
            u64t a0 = a0p[kk], a1 = a1p[kk], a2 = a2p[kk];
            u64t b0 = b0p[kk], b1 = b1p[kk], b2 = b2p[kk];
            ffma2(acc2[0][0], a0, b0);
            ffma2(acc2[0][1], a0, b1);
            ffma2(acc2[0][2], a0, b2);
            ffma2(acc2[1][0], a1, b0);
            ffma2(acc2[1][1], a1, b1);
            ffma2(acc2[1][2], a1, b2);
            ffma2(acc2[2][0], a2, b0);
            ffma2(acc2[2][1], a2, b1);
            ffma2(acc2[2][2], a2, b2);
        }
        __syncthreads();
    }
    float* pr = &part[((size_t)blockIdx.x * 16 + bh) * (CH * CH)];
#pragma unroll
    for (int r = 0; r < 3; r++)
#pragma unroll
        for (int c = 0; c < 3; c++)
            pr[(i0 + r) * CH + (j0 + c)] = pair_sum(acc2[r][c]);
    if (tid < 96)
        cnp[((size_t)blockIdx.x * 16 + bh) * 96 + tid] = nrm;
}

// ------- channel branch: combined top-k softmax coefficients ----------------
__global__ __launch_bounds__(256) void chan_coef_kernel(
    const float* __restrict__ part, const float* __restrict__ cnp,
    const float* __restrict__ temp,
    const float* __restrict__ w1p, const float* __restrict__ w2p,
    const float* __restrict__ w3p, const float* __restrict__ w4p,
    float* __restrict__ coef)
{
    const int warp = threadIdx.x >> 5, ln = threadIdx.x & 31;
    const int row = blockIdx.x * 8 + warp;
    const int bh = row / CH, i = row % CH;
    const int h = bh & 7;
    const float t = temp[h];
    const int KT[4] = {23, 31, 35, 37};
    float wts[4] = {w1p[0], w2p[0], w3p[0], w4p[0]};

    __shared__ float sa[8][CH];
    __shared__ float sth[8][4];

    int j0 = ln, j1 = ln + 32;
    float d0 = 0.f, d1 = 0.f, sqi = 0.f, skk0 = 0.f, skk1 = 0.f;
    for (int s = 0; s < CSPLIT; s++) {
        const float* pr = part + ((size_t)s * 16 + bh) * (CH * CH) + i * CH;
        const float* np = cnp + ((size_t)s * 16 + bh) * 96;
        d0 += pr[j0];
        sqi += np[i];
        skk0 += np[48 + j0];
        if (j1 < CH) { d1 += pr[j1]; skk1 += np[48 + j1]; }
    }
    float inq = 1.f / fmaxf(sqrtf(sqi), 1e-12f);
    float nk0 = fmaxf(sqrtf(skk0), 1e-12f);
    float nk1 = fmaxf(sqrtf(skk1), 1e-12f);
    float a0 = d0 * inq / nk0 * t;
    float a1 = (j1 < CH) ? d1 * inq / nk1 * t : -INFINITY;
    sa[warp][j0] = a0;
    if (j1 < CH) sa[warp][j1] = a1;
    __syncwarp();

    int r0 = 0, r1 = 0;
    for (int q = 0; q < CH; q++) {
        float aq = sa[warp][q];
        r0 += (aq > a0) || (aq == a0 && q < j0);
        if (j1 < CH) r1 += (aq > a1) || (aq == a1 && q < j1);
    }
#pragma unroll
    for (int kx = 0; kx < 4; kx++) {
        if (r0 == KT[kx]) sth[warp][kx] = a0;
        if (j1 < CH && r1 == KT[kx]) sth[warp][kx] = a1;
    }
    __syncwarp();

    float m = fmaxf(a0, a1);
#pragma unroll
    for (int o = 16; o; o >>= 1) m = fmaxf(m, __shfl_xor_sync(0xffffffffu, m, o));
    float e0 = expf(a0 - m);
    float e1 = (j1 < CH) ? expf(a1 - m) : 0.f;

    float th4[4], z[4];
#pragma unroll
    for (int kx = 0; kx < 4; kx++) {
        th4[kx] = sth[warp][kx];
        z[kx] = (a0 >= th4[kx] ? e0 : 0.f) + ((j1 < CH && a1 >= th4[kx]) ? e1 : 0.f);
    }
#pragma unroll
    for (int o = 16; o; o >>= 1) {
        z[0] += __shfl_xor_sync(0xffffffffu, z[0], o);
        z[1] += __shfl_xor_sync(0xffffffffu, z[1], o);
        z[2] += __shfl_xor_sync(0xffffffffu, z[2], o);
        z[3] += __shfl_xor_sync(0xffffffffu, z[3], o);
    }
    float c0 = 0.f, c1 = 0.f;
#pragma unroll
    for (int kx = 0; kx < 4; kx++) {
        float f = wts[kx] / z[kx];
        if (a0 >= th4[kx]) c0 += f;
        if (j1 < CH && a1 >= th4[kx]) c1 += f;
    }
    coef[row * CH + j0] = e0 * c0;
    if (j1 < CH) coef[row * CH + j1] = e1 * c1;
}

// ------- cout = coef @ vc, packed i-pairs, broadcast shared loads -----------
__global__ __launch_bounds__(256) void cout_kernel(
    const float* __restrict__ coef, const float* __restrict__ dw,
    float* __restrict__ out)
{
    int bh = blockIdx.y; int b = bh >> 3, h = bh & 7;
    int p = blockIdx.x * 256 + threadIdx.x;
    __shared__ u64t scp[CH][CH / 2];
    const float* cf = coef + bh * CH * CH;
    for (int e = threadIdx.x; e < CH * (CH / 2); e += 256) {
        int j = e / (CH / 2), i2 = e % (CH / 2);
        scp[j][i2] = pack2(cf[(2 * i2) * CH + j], cf[(2 * i2 + 1) * CH + j]);
    }
    __syncthreads();
    const float* vb = dw + ((size_t)b * NQKV + 2 * NCH + h * CH) * P_PIX + p;
    u64t acc2[CH / 2];
#pragma unroll
    for (int i = 0; i < CH / 2; i++) acc2[i] = 0ull;
    for (int j = 0; j < CH; j++) {
        u64t vd = dup_f32(vb[(size_t)j * P_PIX]);
#pragma unroll
        for (int i = 0; i < CH / 2; i++) ffma2(acc2[i], vd, scp[j][i]);
    }
    float* ob = out + ((size_t)b * NCH + h * CH) * P_PIX + p;
#pragma unroll
    for (int i = 0; i < CH / 2; i++) {
        float lo, hi;
        asm("mov.b64 {%0, %1}, %2;" : "=f"(lo), "=f"(hi) : "l"(acc2[i]));
        ob[(size_t)(2 * i) * P_PIX]     = lo;
        ob[(size_t)(2 * i + 1) * P_PIX] = hi;
    }
}

// ------------- fused spatial window attention, register-tiled + f32x2 --------
#define SQ_STR 50
#define SAT_STR 66
__global__ __launch_bounds__(256) void spatial_kernel(
    const float* __restrict__ dw, const float* __restrict__ temp,
    const float* __restrict__ w1p, const float* __restrict__ w2p,
    const float* __restrict__ w3p, const float* __restrict__ w4p,
    float* __restrict__ out)
{
    extern __shared__ float smemf[];
    float* sq  = smemf;                      // 64*50 (later reused as obuf 48*66)
    float* sk2 = sq  + 64 * SQ_STR;          // 64*50
    float* svT = sk2 + 64 * SQ_STR;          // 48*66
    float* sat = svT + 48 * SAT_STR;         // 64*66
    float* nq  = sat + 64 * SAT_STR;         // 64
    float* nk  = nq  + 64;                   // 64
    float* sth = nk  + 64;                   // 64*4

    const int win = blockIdx.x;
    const int head = blockIdx.y;
    const int b = win >> 8, wy = (win >> 4) & 15, wx = win & 15;
    const int tid = threadIdx.x;
    const int ti = tid >> 4, tj = tid & 15;

    const size_t base = ((size_t)b * NQKV + head * CH) * P_PIX + (size_t)(wy * 8) * 128 + wx * 8;

    for (int e = tid; e < NWIN * CH; e += 256) {
        int c = e >> 6, n = e & 63;
        int iy = n >> 3, ix = n & 7;
        size_t off = (size_t)c * P_PIX + iy * 128 + ix;
        sq [n * SQ_STR + c] = dw[base + off];
        sk2[n * SQ_STR + c] = dw[base + (size_t)NCH * P_PIX + off];
        svT[c * SAT_STR + n] = dw[base + (size_t)(2 * NCH) * P_PIX + off];
    }
    __syncthreads();

    if (tid < 128) {
        int n = tid & 63;
        const float* src = (tid < 64) ? sq : sk2;
        float s = 0.f;
#pragma unroll
        for (int c = 0; c < CH; c++) { float v = src[n * SQ_STR + c]; s = fmaf(v, v, s); }
        float nn = fmaxf(sqrtf(s), 1e-12f);
        if (tid < 64) nq[n] = nn; else nk[n] = nn;
    }
    __syncthreads();

    const float t = temp[wx & 7];
    // QK^T: 4x4 tile per thread, interleaved, f32x2 over channel pairs
    {
        u64t accq2[4][4];
#pragma unroll
        for (int i = 0; i < 4; i++)
#pragma unroll
            for (int j = 0; j < 4; j++) accq2[i][j] = 0ull;
        const u64t* qp[4];
        const u64t* kp[4];
#pragma unroll
        for (int i = 0; i < 4; i++) qp[i] = reinterpret_cast<const u64t*>(&sq[(ti + 16 * i) * SQ_STR]);
#pragma unroll
        for (int j = 0; j < 4; j++) kp[j] = reinterpret_cast<const u64t*>(&sk2[(tj + 16 * j) * SQ_STR]);
#pragma unroll 4
        for (int c2 = 0; c2 < CH / 2; c2++) {
            u64t qv[4], kv[4];
#pragma unroll
            for (int i = 0; i < 4; i++) qv[i] = qp[i][c2];
#pragma unroll
            for (int j = 0; j < 4; j++) kv[j] = kp[j][c2];
#pragma unroll
            for (int i = 0; i < 4; i++)
#pragma unroll
                for (int j = 0; j < 4; j++)
                    ffma2(accq2[i][j], qv[i], kv[j]);
        }
        float qn[4], kn[4];
#pragma unroll
        for (int i = 0; i < 4; i++) qn[i] = nq[ti + 16 * i];
#pragma unroll
        for (int j = 0; j < 4; j++) kn[j] = nk[tj + 16 * j];
#pragma unroll
        for (int i = 0; i < 4; i++)
#pragma unroll
            for (int j = 0; j < 4; j++)
                sat[(ti + 16 * i) * SAT_STR + tj + 16 * j] =
                    pair_sum(accq2[i][j]) / (qn[i] * kn[j]) * t;
    }
    __syncthreads();

    const int warp = tid >> 5, ln = tid & 31;
    const int KT[4] = {31, 41, 47, 50};
    float wts[4] = {w1p[0], w2p[0], w3p[0], w4p[0]};

    for (int rr = 0; rr < 8; rr++) {
        int n = warp * 8 + rr;
        float a0 = sat[n * SAT_STR + ln];
        float a1 = sat[n * SAT_STR + ln + 32];
        int r0 = 0, r1 = 0;
        for (int i2 = 0; i2 < NWIN; i2++) {
            float ai = sat[n * SAT_STR + i2];
            r0 += (ai > a0) || (ai == a0 && i2 < ln);
            r1 += (ai > a1) || (ai == a1 && i2 < ln + 32);
        }
#pragma unroll
        for (int kx = 0; kx < 4; kx++) {
            if (r0 == KT[kx]) sth[n * 4 + kx] = a0;
            if (r1 == KT[kx]) sth[n * 4 + kx] = a1;
        }
        __syncwarp();

        float m = fmaxf(a0, a1);
#pragma unroll
        for (int o = 16; o; o >>= 1) m = fmaxf(m, __shfl_xor_sync(0xffffffffu, m, o));
        float e0 = expf(a0 - m), e1 = expf(a1 - m);

        float th4[4], z[4];
#pragma unroll
        for (int kx = 0; kx < 4; kx++) {
            th4[kx] = sth[n * 4 + kx];
            z[kx] = (a0 >= th4[kx] ? e0 : 0.f) + (a1 >= th4[kx] ? e1 : 0.f);
        }
#pragma unroll
        for (int o = 16; o; o >>= 1) {
            z[0] += __shfl_xor_sync(0xffffffffu, z[0], o);
            z[1] += __shfl_xor_sync(0xffffffffu, z[1], o);
            z[2] += __shfl_xor_sync(0xffffffffu, z[2], o);
            z[3] += __shfl_xor_sync(0xffffffffu, z[3], o);
        }
        float c0 = 0.f, c1 = 0.f;
#pragma unroll
        for (int kx = 0; kx < 4; kx++) {
            float f = wts[kx] / z[kx];
            if (a0 >= th4[kx]) c0 += f;
            if (a1 >= th4[kx]) c1 += f;
        }
        __syncwarp();
        sat[n * SAT_STR + ln]      = e0 * c0;
        sat[n * SAT_STR + ln + 32] = e1 * c1;
        __syncwarp();
    }
    __syncthreads();

    // A*V: 3x4 tile per thread, f32x2 over m pairs; stage in obuf (= sq)
    {
        u64t acca2[3][4];
#pragma unroll
        for (int i = 0; i < 3; i++)
#pragma unroll
            for (int j = 0; j < 4; j++) acca2[i][j] = 0ull;
        const u64t* ap[4];
        const u64t* vp[3];
#pragma unroll
        for (int j = 0; j < 4; j++) ap[j] = reinterpret_cast<const u64t*>(&sat[(ti + 16 * j) * SAT_STR]);
#pragma unroll
        for (int i = 0; i < 3; i++) vp[i] = reinterpret_cast<const u64t*>(&svT[(tj + 16 * i) * SAT_STR]);
#pragma unroll 4
        for (int m2 = 0; m2 < NWIN / 2; m2++) {
            u64t av[4], vv[3];
#pragma unroll
            for (int j = 0; j < 4; j++) av[j] = ap[j][m2];
#pragma unroll
            for (int i = 0; i < 3; i++) vv[i] = vp[i][m2];
#pragma unroll
            for (int i = 0; i < 3; i++)
#pragma unroll
                for (int j = 0; j < 4; j++)
                    ffma2(acca2[i][j], av[j], vv[i]);
        }
        float* obuf = sq;
#pragma unroll
        for (int i = 0; i < 3; i++)
#pragma unroll
            for (int j = 0; j < 4; j++)
                obuf[(tj + 16 * i) * SAT_STR + ti + 16 * j] = pair_sum(acca2[i][j]);
    }
    __syncthreads();

    {
        const float* obuf = sq;
#pragma unroll
        for (int o = 0; o < 12; o++) {
            int e = tid + o * 256;
            int c = e >> 6, n = e & 63;
            int p = wy * 1024 + wx * 64 + n;
            size_t oidx = ((size_t)b * NCH + head * CH + c) * P_PIX + p;
            out[oidx] += obuf[c * SAT_STR + n];
        }
    }
}

// ---------------- host launcher ----------------
extern "C" void kernel_launch(void* const* d_in, const int* in_sizes, int n_in,
                              void* d_out, int out_size)
{
    const float* x      = (const float*)d_in[0];
    const float* w_qkv  = (const float*)d_in[1];
    const float* w_dw   = (const float*)d_in[2];
    const float* w_proj = (const float*)d_in[3];
    const float* temp   = (const float*)d_in[4];
    const float* a1     = (const float*)d_in[5];
    const float* a2     = (const float*)d_in[6];
    const float* a3     = (const float*)d_in[7];
    const float* a4     = (const float*)d_in[8];
    float* out = (float*)d_out;

    float *qkv, *dwb, *sum, *cpart, *cnp, *ccoef;
    __nv_bfloat16 *xth, *xtl, *wqh, *wql, *wph, *wpl;
    cudaGetSymbolAddress((void**)&qkv,   g_qkv);
    cudaGetSymbolAddress((void**)&dwb,   g_dw);
    cudaGetSymbolAddress((void**)&sum,   g_sum);
    cudaGetSymbolAddress((void**)&cpart, g_cpart);
    cudaGetSymbolAddress((void**)&cnp,   g_cnp);
    cudaGetSymbolAddress((void**)&ccoef, g_ccoef);
    cudaGetSymbolAddress((void**)&xth,   g_xth);
    cudaGetSymbolAddress((void**)&xtl,   g_xtl);
    cudaGetSymbolAddress((void**)&wqh,   g_wqh);
    cudaGetSymbolAddress((void**)&wql,   g_wql);
    cudaGetSymbolAddress((void**)&wph,   g_wph);
    cudaGetSymbolAddress((void**)&wpl,   g_wpl);

    const int spatial_smem =
        (64 * SQ_STR * 2 + 48 * SAT_STR + 64 * SAT_STR + 64 + 64 + 64 * 4) * 4;
    const int gemm_smem = 2 * 4 * AS * 2;   // 81920 B
    cudaFuncSetAttribute(spatial_kernel, cudaFuncAttributeMaxDynamicSharedMemorySize, 65536);
    cudaFuncSetAttribute(hmma_gemm, cudaFuncAttributeMaxDynamicSharedMemorySize, gemm_smem);

    // 0) weight splits + X transpose/split
    convert_w<<<(NQKV * NCH + 255) / 256, 256>>>(w_qkv, wqh, wql, NQKV * NCH);
    convert_w<<<(NCH * NCH + 255) / 256, 256>>>(w_proj, wph, wpl, NCH * NCH);
    transpose_split<<<dim3(P_PIX / 32, GK / 32, 2), 256>>>(x, xth, xtl);
    // 1) qkv = 1x1 conv via split-bf16 HMMA (M=1152)
    hmma_gemm<<<dim3(P_PIX / 128, NQKV / 128, 2), 256, gemm_smem>>>(wqh, wql, xth, xtl, qkv, NQKV);
    // 2) depthwise 3x3 (2x4 tile per thread)
    dwconv_kernel<<<(2 * NQKV * P_PIX / 8) / 256, 256>>>(qkv, w_dw, dwb);
    // 3) cattn split-K partials + fused row norms (f32x2)
    cattn_kernel<<<dim3(CSPLIT, 16), 256>>>(dwb, cpart, cnp);
    // 4) channel softmax coefficients (reduces norms inline)
    chan_coef_kernel<<<96, 256>>>(cpart, cnp, temp, a1, a2, a3, a4, ccoef);
    // 5) cout = coef @ v
    cout_kernel<<<dim3(P_PIX / 256, 16), 256>>>(ccoef, dwb, sum);
    // 6) fused spatial window attention (adds into g_sum, f32x2)
    spatial_kernel<<<dim3(512, HEADS), 256, spatial_smem>>>(dwb, temp, a1, a2, a3, a4, sum);
    // 7) proj: transpose/split g_sum, then HMMA GEMM (M=384) -> d_out
    transpose_split<<<dim3(P_PIX / 32, GK / 32, 2), 256>>>(sum, xth, xtl);
    hmma_gemm<<<dim3(P_PIX / 128, NCH / 128, 2), 256, gemm_smem>>>(wph, wpl, xth, xtl, out, NCH);
}

// round 16
// speedup vs baseline: 1.1108x; 1.0152x over previous
#include <cuda_runtime.h>
#include <cuda_bf16.h>
#include <math.h>
#include <cstdint>

#define P_PIX 16384   // 128*128
#define NCH   384
#define NQKV  1152
#define HEADS 8
#define CH    48      // per-head channels
#define NWIN  64      // tokens per 8x8 window
#define CSPLIT 32     // cattn K splits
#define GK    384     // GEMM K (both gemms)
#define BK    32      // K chunk (cp.async stage)
#define NKC   (GK / BK)   // 12 chunks
#define A_STR 40      // smem row stride (bf16), 80B: conflict-free ldmatrix
#define AS    (128 * A_STR)   // elems per array tile

typedef unsigned long long u64t;

__device__ __forceinline__ u64t dup_f32(float a) {
    u64t r; asm("mov.b64 %0, {%1, %1};" : "=l"(r) : "f"(a)); return r;
}
__device__ __forceinline__ void ffma2(u64t& acc, u64t a, u64t b) {
    asm("fma.rn.f32x2 %0, %1, %2, %0;" : "+l"(acc) : "l"(a), "l"(b));
}
__device__ __forceinline__ float pair_sum(u64t v) {
    float lo, hi; asm("mov.b64 {%0, %1}, %2;" : "=f"(lo), "=f"(hi) : "l"(v)); return lo + hi;
}
__device__ __forceinline__ uint32_t smem_u32(const void* p) {
    uint32_t a;
    asm("{ .reg .u64 t; cvta.to.shared.u64 t, %1; cvt.u32.u64 %0, t; }" : "=r"(a) : "l"(p));
    return a;
}
__device__ __forceinline__ void ldsm_x4(uint32_t* r, uint32_t addr) {
    asm volatile("ldmatrix.sync.aligned.m8n8.x4.shared.b16 {%0,%1,%2,%3}, [%4];"
                 : "=r"(r[0]), "=r"(r[1]), "=r"(r[2]), "=r"(r[3]) : "r"(addr));
}
__device__ __forceinline__ void ldsm_x2(uint32_t* r, uint32_t addr) {
    asm volatile("ldmatrix.sync.aligned.m8n8.x2.shared.b16 {%0,%1}, [%2];"
                 : "=r"(r[0]), "=r"(r[1]) : "r"(addr));
}
__device__ __forceinline__ void mma_bf16(float* c, const uint32_t* a, const uint32_t* b) {
    asm volatile("mma.sync.aligned.m16n8k16.row.col.f32.bf16.bf16.f32 "
                 "{%0,%1,%2,%3}, {%4,%5,%6,%7}, {%8,%9}, {%0,%1,%2,%3};"
                 : "+f"(c[0]), "+f"(c[1]), "+f"(c[2]), "+f"(c[3])
                 : "r"(a[0]), "r"(a[1]), "r"(a[2]), "r"(a[3]), "r"(b[0]), "r"(b[1]));
}
__device__ __forceinline__ void cp_async16(uint32_t saddr, const void* g) {
    asm volatile("cp.async.cg.shared.global [%0], [%1], 16;" :: "r"(saddr), "l"(g));
}
#define CP_COMMIT() asm volatile("cp.async.commit_group;" ::: "memory")
#define CP_WAIT1()  asm volatile("cp.async.wait_group 1;" ::: "memory")
#define CP_WAIT0()  asm volatile("cp.async.wait_group 0;" ::: "memory")

// ---------------- scratch (device globals; no allocs allowed) ----------------
__device__ float g_qkv[2ll * NQKV * P_PIX];
__device__ float g_dw [2ll * NQKV * P_PIX];
__device__ float g_cpart[CSPLIT * 16 * CH * CH];
__device__ float g_cnp[CSPLIT * 16 * 96];      // per-split row sum-of-squares (48 q + 48 k)
__device__ float g_ccoef[16 * CH * CH];
__device__ __nv_bfloat16 g_xth[2ll * P_PIX * GK];
__device__ __nv_bfloat16 g_xtl[2ll * P_PIX * GK];
__device__ __nv_bfloat16 g_wqh[NQKV * NCH];
__device__ __nv_bfloat16 g_wql[NQKV * NCH];
__device__ __nv_bfloat16 g_wph[NCH * NCH];
__device__ __nv_bfloat16 g_wpl[NCH * NCH];

// ---------------- weight split fp32 -> bf16 hi/lo ----------------
__global__ __launch_bounds__(256) void convert_w(
    const float* __restrict__ W, __nv_bfloat16* __restrict__ Wh,
    __nv_bfloat16* __restrict__ Wl, int n)
{
    int i = blockIdx.x * 256 + threadIdx.x;
    if (i >= n) return;
    float v = W[i];
    __nv_bfloat16 hi = __float2bfloat16(v);
    Wh[i] = hi;
    Wl[i] = __float2bfloat16(v - __bfloat162float(hi));
}

// ------- transpose+split: X fp32 [b][K=384][16384] -> T bf16 [b][16384][384] --
__global__ __launch_bounds__(256) void transpose_split(
    const float* __restrict__ X, __nv_bfloat16* __restrict__ Th,
    __nv_bfloat16* __restrict__ Tl)
{
    __shared__ float s[32][33];
    const int b  = blockIdx.z;
    const int p0 = blockIdx.x * 32;
    const int k0 = blockIdx.y * 32;
    const int tid = threadIdx.x;
    const int tx = tid & 31, ty = tid >> 5;
    const float* Xb = X + ((size_t)b * GK + k0) * P_PIX + p0;
#pragma unroll
    for (int i = 0; i < 4; i++)
        s[ty + 8 * i][tx] = Xb[(size_t)(ty + 8 * i) * P_PIX + tx];
    __syncthreads();
    const int row = tid >> 3;
    const int kk = (tid & 7) * 4;
    __nv_bfloat16 hv[4], lv[4];
#pragma unroll
    for (int j = 0; j < 4; j++) {
        float v = s[kk + j][row];
        hv[j] = __float2bfloat16(v);
        lv[j] = __float2bfloat16(v - __bfloat162float(hv[j]));
    }
    size_t ob = ((size_t)b * P_PIX + p0 + row) * GK + k0 + kk;
    *reinterpret_cast<__nv_bfloat162*>(&Th[ob])     = *reinterpret_cast<__nv_bfloat162*>(&hv[0]);
    *reinterpret_cast<__nv_bfloat162*>(&Th[ob + 2]) = *reinterpret_cast<__nv_bfloat162*>(&hv[2]);
    *reinterpret_cast<__nv_bfloat162*>(&Tl[ob])     = *reinterpret_cast<__nv_bfloat162*>(&lv[0]);
    *reinterpret_cast<__nv_bfloat162*>(&Tl[ob + 2]) = *reinterpret_cast<__nv_bfloat162*>(&lv[2]);
}

// ------------- split-bf16 HMMA GEMM, cp.async double-buffered (R9 config) ----
__global__ __launch_bounds__(256, 2) void hmma_gemm(
    const __nv_bfloat16* __restrict__ Wh, const __nv_bfloat16* __restrict__ Wl,
    const __nv_bfloat16* __restrict__ Th, const __nv_bfloat16* __restrict__ Tl,
    float* __restrict__ Y, int M)
{
    extern __shared__ __nv_bfloat16 sm[];
    const uint32_t sm32 = smem_u32(sm);

    const int tid = threadIdx.x;
    const int wid = tid >> 5, lane = tid & 31;
    const int wr = wid >> 2;          // 0..1
    const int wc = wid & 3;           // 0..3
    const int b  = blockIdx.z;
    const int m0 = blockIdx.y * 128;
    const int p0 = blockIdx.x * 128;

    const __nv_bfloat16* gA[4];
    gA[0] = Wh + (size_t)m0 * GK;
    gA[1] = Wl + (size_t)m0 * GK;
    gA[2] = Th + ((size_t)b * P_PIX + p0) * GK;
    gA[3] = Tl + ((size_t)b * P_PIX + p0) * GK;

    float acc[4][4][4];
#pragma unroll
    for (int i = 0; i < 4; i++)
#pragma unroll
        for (int j = 0; j < 4; j++)
#pragma unroll
            for (int r = 0; r < 4; r++) acc[i][j][r] = 0.f;

    auto issue = [&](int chunk, int buf) {
        const int kb = chunk * BK;
        const uint32_t bufb = sm32 + (uint32_t)buf * 4 * AS * 2;
#pragma unroll
        for (int i = 0; i < 2; i++) {
            int idx = tid + i * 256;             // 0..511
            int row = idx >> 2, c8 = (idx & 3) * 8;
            size_t go = (size_t)row * GK + kb + c8;
            uint32_t so = bufb + (uint32_t)(row * A_STR + c8) * 2;
#pragma unroll
            for (int a = 0; a < 4; a++)
                cp_async16(so + (uint32_t)a * AS * 2, gA[a] + go);
        }
        CP_COMMIT();
    };

    issue(0, 0);
    issue(1, 1);

    for (int c = 0; c < NKC; c++) {
        if (c + 1 < NKC) CP_WAIT1(); else CP_WAIT0();
        __syncthreads();
        const uint32_t bufb = sm32 + (uint32_t)(c & 1) * 4 * AS * 2;
        const uint32_t sAh32 = bufb;
        const uint32_t sAl32 = bufb + AS * 2;
        const uint32_t sBh32 = bufb + 2 * AS * 2;
        const uint32_t sBl32 = bufb + 3 * AS * 2;

#pragma unroll
        for (int ks = 0; ks < BK / 16; ks++) {
            const int k0 = ks * 16;
            const int nrow = wc * 32 + (lane & 7);
            const int ncol = k0 + ((lane >> 3) & 1) * 8;
            const int arow = wr * 64 + (lane & 15);
            const int acol = k0 + (lane >> 4) * 8;

            uint32_t bH[4][2], aH[4][4];
#pragma unroll
            for (int nt = 0; nt < 4; nt++)
                ldsm_x2(bH[nt], sBh32 + (uint32_t)((nrow + nt * 8) * A_STR + ncol) * 2);
#pragma unroll
            for (int mt = 0; mt < 4; mt++)
                ldsm_x4(aH[mt], sAh32 + (uint32_t)((arow + mt * 16) * A_STR + acol) * 2);
#pragma unroll
            for (int mt = 0; mt < 4; mt++)
#pragma unroll
                for (int nt = 0; nt < 4; nt++)
                    mma_bf16(acc[mt][nt], aH[mt], bH[nt]);
            uint32_t bL[4][2];
#pragma unroll
            for (int nt = 0; nt < 4; nt++)
                ldsm_x2(bL[nt], sBl32 + (uint32_t)((nrow + nt * 8) * A_STR + ncol) * 2);
#pragma unroll
            for (int mt = 0; mt < 4; mt++)
#pragma unroll
                for (int nt = 0; nt < 4; nt++)
                    mma_bf16(acc[mt][nt], aH[mt], bL[nt]);
            uint32_t aL[4][4];
#pragma unroll
            for (int mt = 0; mt < 4; mt++)
                ldsm_x4(aL[mt], sAl32 + (uint32_t)((arow + mt * 16) * A_STR + acol) * 2);
#pragma unroll
            for (int mt = 0; mt < 4; mt++)
#pragma unroll
                for (int nt = 0; nt < 4; nt++)
                    mma_bf16(acc[mt][nt], aL[mt], bH[nt]);
        }
        __syncthreads();
        if (c + 2 < NKC) issue(c + 2, c & 1);
    }

    // epilogue
    const int tq = lane >> 2;
    const int tr4 = lane & 3;
#pragma unroll
    for (int mt = 0; mt < 4; mt++) {
#pragma unroll
        for (int nt = 0; nt < 4; nt++) {
            int m  = m0 + wr * 64 + mt * 16 + tq;
            int p  = p0 + wc * 32 + nt * 8 + tr4 * 2;
            float* y0 = &Y[((size_t)b * M + m) * P_PIX + p];
            *reinterpret_cast<float2*>(y0) = make_float2(acc[mt][nt][0], acc[mt][nt][1]);
            float* y1 = &Y[((size_t)b * M + m + 8) * P_PIX + p];
            *reinterpret_cast<float2*>(y1) = make_float2(acc[mt][nt][2], acc[mt][nt][3]);
        }
    }
}

// ---------------- depthwise 3x3, pad 1, 2-tall x 4-wide per thread ----------
__global__ __launch_bounds__(256) void dwconv_kernel(
    const float* __restrict__ in, const float* __restrict__ Wd, float* __restrict__ out)
{
    int gid = blockIdx.x * 256 + threadIdx.x;      // 2*1152*2048
    int grp = gid & 2047;
    int bc  = gid >> 11;
    int ch  = bc % NQKV;
    int x0 = (grp & 31) * 4, y0 = (grp >> 5) * 2;
    const float* ip = in + (size_t)bc * P_PIX;
    const float* w  = Wd + ch * 9;
    float o0[4] = {0.f, 0.f, 0.f, 0.f};
    float o1[4] = {0.f, 0.f, 0.f, 0.f};
#pragma unroll
    for (int r = 0; r < 4; r++) {                  // input rows y0-1 .. y0+2
        int yy = y0 - 1 + r;
        if ((unsigned)yy >= 128u) continue;
        const float* rp = ip + yy * 128;
        float v[6];
#pragma unroll
        for (int t = 0; t < 6; t++) {
            int xx = x0 - 1 + t;
            v[t] = ((unsigned)xx < 128u) ? rp[xx] : 0.f;
        }
#pragma unroll
        for (int dx = 0; dx < 3; dx++) {
            if (r < 3) {
                float wv = w[r * 3 + dx];
#pragma unroll
                for (int i = 0; i < 4; i++) o0[i] = fmaf(wv, v[dx + i], o0[i]);
            }
            if (r >= 1) {
                float wv = w[(r - 1) * 3 + dx];
#pragma unroll
                for (int i = 0; i < 4; i++) o1[i] = fmaf(wv, v[dx + i], o1[i]);
            }
        }
    }
    float* ob = out + (size_t)bc * P_PIX + y0 * 128 + x0;
    *reinterpret_cast<float4*>(ob)       = make_float4(o0[0], o0[1], o0[2], o0[3]);
    *reinterpret_cast<float4*>(ob + 128) = make_float4(o1[0], o1[1], o1[2], o1[3]);
}

// ------ cattn raw dots + fused row sumsq, split-K partials, f32x2 -----------
__global__ __launch_bounds__(256) void cattn_kernel(
    const float* __restrict__ dw, float* __restrict__ part, float* __restrict__ cnp)
{
    const int bh = blockIdx.y;
    const int b = bh >> 3, h = bh & 7;
    const int kbase = blockIdx.x * (P_PIX / CSPLIT);
    const float* qb = dw + ((size_t)b * NQKV + h * CH) * P_PIX;
    const float* kb = dw + ((size_t)b * NQKV + NCH + h * CH) * P_PIX;

    __shared__ float sq[CH][66];   // even stride: 8B-aligned rows for LDS.64
    __shared__ float sk[CH][66];

    const int tid = threadIdx.x;
    const int ti = tid >> 4, tj = tid & 15;
    const int i0 = ti * 3, j0 = tj * 3;

    u64t acc2[3][3];
#pragma unroll
    for (int r = 0; r < 3; r++)
#pragma unroll
        for (int c = 0; c < 3; c++) acc2[r][c] = 0ull;
    float nrm = 0.f;

    for (int kc = 0; kc < P_PIX / CSPLIT; kc += 64) {
        const int kpos = kbase + kc;
        for (int e = tid; e < CH * 16; e += 256) {
            int r = e >> 4, c4 = (e & 15) * 4;
            float4 vq = *reinterpret_cast<const float4*>(&qb[(size_t)r * P_PIX + kpos + c4]);
            float4 vk = *reinterpret_cast<const float4*>(&kb[(size_t)r * P_PIX + kpos + c4]);
            sq[r][c4] = vq.x; sq[r][c4+1] = vq.y; sq[r][c4+2] = vq.z; sq[r][c4+3] = vq.w;
            sk[r][c4] = vk.x; sk[r][c4+1] = vk.y; sk[r][c4+2] = vk.z; sk[r][c4+3] = vk.w;
        }
        __syncthreads();
        if (tid < 96) {
            const float* rowp = (tid < 48) ? &sq[tid][0] : &sk[tid - 48][0];
#pragma unroll 16
            for (int c = 0; c < 64; c++) nrm = fmaf(rowp[c], rowp[c], nrm);
        }
        const u64t* a0p = reinterpret_cast<const u64t*>(&sq[i0][0]);
        const u64t* a1p = reinterpret_cast<const u64t*>(&sq[i0 + 1][0]);
        const u64t* a2p = reinterpret_cast<const u64t*>(&sq[i0 + 2][0]);
        const u64t* b0p = reinterpret_cast<const u64t*>(&sk[j0][0]);
        const u64t* b1p = reinterpret_cast<const u64t*>(&sk[j0 + 1][0]);
        const u64t* b2p = reinterpret_cast<const u64t*>(&sk[j0 + 2][0]);
#pragma unroll 8
        for (int kk = 0; kk < 32; kk++) {
            u64t a0 = a0p[kk], a1 = a1p[kk], a2 = a2p[kk];
            u64t b0 = b0p[kk], b1 = b1p[kk], b2 = b2p[kk];
            ffma2(acc2[0][0], a0, b0);
            ffma2(acc2[0][1], a0, b1);
            ffma2(acc2[0][2], a0, b2);
            ffma2(acc2[1][0], a1, b0);
            ffma2(acc2[1][1], a1, b1);
            ffma2(acc2[1][2], a1, b2);
            ffma2(acc2[2][0], a2, b0);
            ffma2(acc2[2][1], a2, b1);
            ffma2(acc2[2][2], a2, b2);
        }
        __syncthreads();
    }
    float* pr = &part[((size_t)blockIdx.x * 16 + bh) * (CH * CH)];
#pragma unroll
    for (int r = 0; r < 3; r++)
#pragma unroll
        for (int c = 0; c < 3; c++)
            pr[(i0 + r) * CH + (j0 + c)] = pair_sum(acc2[r][c]);
    if (tid < 96)
        cnp[((size_t)blockIdx.x * 16 + bh) * 96 + tid] = nrm;
}

// ------- channel branch: combined top-k softmax coefficients ----------------
__global__ __launch_bounds__(256) void chan_coef_kernel(
    const float* __restrict__ part, const float* __restrict__ cnp,
    const float* __restrict__ temp,
    const float* __restrict__ w1p, const float* __restrict__ w2p,
    const float* __restrict__ w3p, const float* __restrict__ w4p,
    float* __restrict__ coef)
{
    const int warp = threadIdx.x >> 5, ln = threadIdx.x & 31;
    const int row = blockIdx.x * 8 + warp;
    const int bh = row / CH, i = row % CH;
    const int h = bh & 7;
    const float t = temp[h];
    const int KT[4] = {23, 31, 35, 37};
    float wts[4] = {w1p[0], w2p[0], w3p[0], w4p[0]};

    __shared__ float sa[8][CH];
    __shared__ float sth[8][4];

    int j0 = ln, j1 = ln + 32;
    float d0 = 0.f, d1 = 0.f, sqi = 0.f, skk0 = 0.f, skk1 = 0.f;
    for (int s = 0; s < CSPLIT; s++) {
        const float* pr = part + ((size_t)s * 16 + bh) * (CH * CH) + i * CH;
        const float* np = cnp + ((size_t)s * 16 + bh) * 96;
        d0 += pr[j0];
        sqi += np[i];
        skk0 += np[48 + j0];
        if (j1 < CH) { d1 += pr[j1]; skk1 += np[48 + j1]; }
    }
    float inq = 1.f / fmaxf(sqrtf(sqi), 1e-12f);
    float nk0 = fmaxf(sqrtf(skk0), 1e-12f);
    float nk1 = fmaxf(sqrtf(skk1), 1e-12f);
    float a0 = d0 * inq / nk0 * t;
    float a1 = (j1 < CH) ? d1 * inq / nk1 * t : -INFINITY;
    sa[warp][j0] = a0;
    if (j1 < CH) sa[warp][j1] = a1;
    __syncwarp();

    int r0 = 0, r1 = 0;
    for (int q = 0; q < CH; q++) {
        float aq = sa[warp][q];
        r0 += (aq > a0) || (aq == a0 && q < j0);
        if (j1 < CH) r1 += (aq > a1) || (aq == a1 && q < j1);
    }
#pragma unroll
    for (int kx = 0; kx < 4; kx++) {
        if (r0 == KT[kx]) sth[warp][kx] = a0;
        if (j1 < CH && r1 == KT[kx]) sth[warp][kx] = a1;
    }
    __syncwarp();

    float m = fmaxf(a0, a1);
#pragma unroll
    for (int o = 16; o; o >>= 1) m = fmaxf(m, __shfl_xor_sync(0xffffffffu, m, o));
    float e0 = expf(a0 - m);
    float e1 = (j1 < CH) ? expf(a1 - m) : 0.f;

    float th4[4], z[4];
#pragma unroll
    for (int kx = 0; kx < 4; kx++) {
        th4[kx] = sth[warp][kx];
        z[kx] = (a0 >= th4[kx] ? e0 : 0.f) + ((j1 < CH && a1 >= th4[kx]) ? e1 : 0.f);
    }
#pragma unroll
    for (int o = 16; o; o >>= 1) {
        z[0] += __shfl_xor_sync(0xffffffffu, z[0], o);
        z[1] += __shfl_xor_sync(0xffffffffu, z[1], o);
        z[2] += __shfl_xor_sync(0xffffffffu, z[2], o);
        z[3] += __shfl_xor_sync(0xffffffffu, z[3], o);
    }
    float c0 = 0.f, c1 = 0.f;
#pragma unroll
    for (int kx = 0; kx < 4; kx++) {
        float f = wts[kx] / z[kx];
        if (a0 >= th4[kx]) c0 += f;
        if (j1 < CH && a1 >= th4[kx]) c1 += f;
    }
    coef[row * CH + j0] = e0 * c0;
    if (j1 < CH) coef[row * CH + j1] = e1 * c1;
}

// ---- fused spatial attention + channel output + transpose/split emit -------
// Channel branch uses V at the SCRAMBLED output pixels pbase..pbase+63
// (contiguous half-row), loaded separately as vout. Produces proj-GEMM
// input directly: Th/Tl [b][p][k=head*48+c] bf16 hi/lo.
#define SQ_STR 50
#define SAT_STR 66
#define CF_STR 50
#define VO_STR 66
__global__ __launch_bounds__(256) void spatial_kernel(
    const float* __restrict__ dw, const float* __restrict__ coef,
    const float* __restrict__ temp,
    const float* __restrict__ w1p, const float* __restrict__ w2p,
    const float* __restrict__ w3p, const float* __restrict__ w4p,
    __nv_bfloat16* __restrict__ Th, __nv_bfloat16* __restrict__ Tl)
{
    extern __shared__ float smemf[];
    float* sq  = smemf;                      // 64*50 q  (later: coefT 48*50)
    float* sk2 = sq  + 64 * SQ_STR;          // 64*50 k  (later: vout 48*66)
    float* svT = sk2 + 64 * SQ_STR;          // 48*66
    float* sat = svT + 48 * SAT_STR;         // 64*66 scores (later: obuf 48*66)
    float* nq  = sat + 64 * SAT_STR;         // 64
    float* nk  = nq  + 64;                   // 64
    float* sth = nk  + 64;                   // 64*4

    const int win = blockIdx.x;
    const int head = blockIdx.y;
    const int b = win >> 8, wy = (win >> 4) & 15, wx = win & 15;
    const int bh = b * 8 + head;
    const int tid = threadIdx.x;
    const int ti = tid >> 4, tj = tid & 15;
    const int pbase = wy * 1024 + wx * 64;

    const size_t base = ((size_t)b * NQKV + head * CH) * P_PIX + (size_t)(wy * 8) * 128 + wx * 8;
    const float* vglob = dw + ((size_t)b * NQKV + 2 * NCH + head * CH) * P_PIX;

    for (int e = tid; e < NWIN * CH; e += 256) {
        int c = e >> 6, n = e & 63;
        int iy = n >> 3, ix = n & 7;
        size_t off = (size_t)c * P_PIX + iy * 128 + ix;
        sq [n * SQ_STR + c] = dw[base + off];
        sk2[n * SQ_STR + c] = dw[base + (size_t)NCH * P_PIX + off];
        svT[c * SAT_STR + n] = dw[base + (size_t)(2 * NCH) * P_PIX + off];
    }
    __syncthreads();

    if (tid < 128) {
        int n = tid & 63;
        const float* src = (tid < 64) ? sq : sk2;
        float s = 0.f;
#pragma unroll
        for (int c = 0; c < CH; c++) { float v = src[n * SQ_STR + c]; s = fmaf(v, v, s); }
        float nn = fmaxf(sqrtf(s), 1e-12f);
        if (tid < 64) nq[n] = nn; else nk[n] = nn;
    }
    __syncthreads();

    const float t = temp[wx & 7];
    // QK^T: 4x4 tile per thread, interleaved, f32x2 over channel pairs
    {
        u64t accq2[4][4];
#pragma unroll
        for (int i = 0; i < 4; i++)
#pragma unroll
            for (int j = 0; j < 4; j++) accq2[i][j] = 0ull;
        const u64t* qp[4];
        const u64t* kp[4];
#pragma unroll
        for (int i = 0; i < 4; i++) qp[i] = reinterpret_cast<const u64t*>(&sq[(ti + 16 * i) * SQ_STR]);
#pragma unroll
        for (int j = 0; j < 4; j++) kp[j] = reinterpret_cast<const u64t*>(&sk2[(tj + 16 * j) * SQ_STR]);
#pragma unroll 4
        for (int c2 = 0; c2 < CH / 2; c2++) {
            u64t qv[4], kv[4];
#pragma unroll
            for (int i = 0; i < 4; i++) qv[i] = qp[i][c2];
#pragma unroll
            for (int j = 0; j < 4; j++) kv[j] = kp[j][c2];
#pragma unroll
            for (int i = 0; i < 4; i++)
#pragma unroll
                for (int j = 0; j < 4; j++)
                    ffma2(accq2[i][j], qv[i], kv[j]);
        }
        float qn[4], kn[4];
#pragma unroll
        for (int i = 0; i < 4; i++) qn[i] = nq[ti + 16 * i];
#pragma unroll
        for (int j = 0; j < 4; j++) kn[j] = nk[tj + 16 * j];
#pragma unroll
        for (int i = 0; i < 4; i++)
#pragma unroll
            for (int j = 0; j < 4; j++)
                sat[(ti + 16 * i) * SAT_STR + tj + 16 * j] =
                    pair_sum(accq2[i][j]) / (qn[i] * kn[j]) * t;
    }
    __syncthreads();   // sq, sk2 now dead

    // coefT[j][c] = coef[c][j] into sq region; vout[c][n] = v[c][pbase+n] into sk2
    float* coefT = sq;
    float* vout  = sk2;
    {
        const float* cf = coef + bh * CH * CH;
        for (int e = tid; e < CH * CH; e += 256) {
            int j = e / CH, c = e % CH;
            coefT[j * CF_STR + c] = cf[c * CH + j];
        }
        for (int e = tid; e < CH * NWIN; e += 256) {
            int c = e >> 6, n = e & 63;
            vout[c * VO_STR + n] = vglob[(size_t)c * P_PIX + pbase + n];
        }
    }

    const int warp = tid >> 5, ln = tid & 31;
    const int KT[4] = {31, 41, 47, 50};
    float wts[4] = {w1p[0], w2p[0], w3p[0], w4p[0]};

    for (int rr = 0; rr < 8; rr++) {
        int n = warp * 8 + rr;
        float a0 = sat[n * SAT_STR + ln];
        float a1 = sat[n * SAT_STR + ln + 32];
        int r0 = 0, r1 = 0;
        for (int i2 = 0; i2 < NWIN; i2++) {
            float ai = sat[n * SAT_STR + i2];
            r0 += (ai > a0) || (ai == a0 && i2 < ln);
            r1 += (ai > a1) || (ai == a1 && i2 < ln + 32);
        }
#pragma unroll
        for (int kx = 0; kx < 4; kx++) {
            if (r0 == KT[kx]) sth[n * 4 + kx] = a0;
            if (r1 == KT[kx]) sth[n * 4 + kx] = a1;
        }
        __syncwarp();

        float m = fmaxf(a0, a1);
#pragma unroll
        for (int o = 16; o; o >>= 1) m = fmaxf(m, __shfl_xor_sync(0xffffffffu, m, o));
        float e0 = expf(a0 - m), e1 = expf(a1 - m);

        float th4[4], z[4];
#pragma unroll
        for (int kx = 0; kx < 4; kx++) {
            th4[kx] = sth[n * 4 + kx];
            z[kx] = (a0 >= th4[kx] ? e0 : 0.f) + (a1 >= th4[kx] ? e1 : 0.f);
        }
#pragma unroll
        for (int o = 16; o; o >>= 1) {
            z[0] += __shfl_xor_sync(0xffffffffu, z[0], o);
            z[1] += __shfl_xor_sync(0xffffffffu, z[1], o);
            z[2] += __shfl_xor_sync(0xffffffffu, z[2], o);
            z[3] += __shfl_xor_sync(0xffffffffu, z[3], o);
        }
        float c0 = 0.f, c1 = 0.f;
#pragma unroll
        for (int kx = 0; kx < 4; kx++) {
            float f = wts[kx] / z[kx];
            if (a0 >= th4[kx]) c0 += f;
            if (a1 >= th4[kx]) c1 += f;
        }
        __syncwarp();
        sat[n * SAT_STR + ln]      = e0 * c0;
        sat[n * SAT_STR + ln + 32] = e1 * c1;
        __syncwarp();
    }
    __syncthreads();

    // A*V (f32x2, window V) + channel branch coef@vout (scrambled-pixel V)
    float res[3][4];
    {
        u64t acca2[3][4];
#pragma unroll
        for (int i = 0; i < 3; i++)
#pragma unroll
            for (int j = 0; j < 4; j++) acca2[i][j] = 0ull;
        const u64t* ap[4];
        const u64t* vp[3];
#pragma unroll
        for (int j = 0; j < 4; j++) ap[j] = reinterpret_cast<const u64t*>(&sat[(ti + 16 * j) * SAT_STR]);
#pragma unroll
        for (int i = 0; i < 3; i++) vp[i] = reinterpret_cast<const u64t*>(&svT[(tj + 16 * i) * SAT_STR]);
#pragma unroll 4
        for (int m2 = 0; m2 < NWIN / 2; m2++) {
            u64t av[4], vv[3];
#pragma unroll
            for (int j = 0; j < 4; j++) av[j] = ap[j][m2];
#pragma unroll
            for (int i = 0; i < 3; i++) vv[i] = vp[i][m2];
#pragma unroll
            for (int i = 0; i < 3; i++)
#pragma unroll
                for (int j = 0; j < 4; j++)
                    ffma2(acca2[i][j], av[j], vv[i]);
        }
        float accc[3][4];
#pragma unroll
        for (int i = 0; i < 3; i++)
#pragma unroll
            for (int j = 0; j < 4; j++) accc[i][j] = 0.f;
#pragma unroll 4
        for (int j = 0; j < CH; j++) {
            float cfv[3], vv[4];
#pragma unroll
            for (int i = 0; i < 3; i++) cfv[i] = coefT[j * CF_STR + tj + 16 * i];
#pragma unroll
            for (int jj = 0; jj < 4; jj++) vv[jj] = vout[j * VO_STR + ti + 16 * jj];
#pragma unroll
            for (int i = 0; i < 3; i++)
#pragma unroll
                for (int jj = 0; jj < 4; jj++)
                    accc[i][jj] = fmaf(cfv[i], vv[jj], accc[i][jj]);
        }
#pragma unroll
        for (int i = 0; i < 3; i++)
#pragma unroll
            for (int j = 0; j < 4; j++)
                res[i][j] = pair_sum(acca2[i][j]) + accc[i][j];
    }
    __syncthreads();   // all sat reads done -> reuse sat region as obuf

    float* obuf = sat;
#pragma unroll
    for (int i = 0; i < 3; i++)
#pragma unroll
        for (int j = 0; j < 4; j++)
            obuf[(tj + 16 * i) * SAT_STR + ti + 16 * j] = res[i][j];
    __syncthreads();

    // emit transposed bf16 hi/lo: Th/Tl[(b*P_PIX + pbase + n)*GK + head*48 + c]
    {
#pragma unroll
        for (int o = 0; o < 6; o++) {
            int e = tid + o * 256;               // 0..1535: n = e/24, c2 = e%24
            int n = e / 24, c = (e % 24) * 2;
            float v0 = obuf[c * SAT_STR + n];
            float v1 = obuf[(c + 1) * SAT_STR + n];
            __nv_bfloat16 h0 = __float2bfloat16(v0);
            __nv_bfloat16 h1 = __float2bfloat16(v1);
            __nv_bfloat16 l0 = __float2bfloat16(v0 - __bfloat162float(h0));
            __nv_bfloat16 l1 = __float2bfloat16(v1 - __bfloat162float(h1));
            size_t ob = ((size_t)b * P_PIX + pbase + n) * GK + head * CH + c;
            *reinterpret_cast<__nv_bfloat162*>(&Th[ob]) = __nv_bfloat162(h0, h1);
            *reinterpret_cast<__nv_bfloat162*>(&Tl[ob]) = __nv_bfloat162(l0, l1);
        }
    }
}

// ---------------- host launcher ----------------
extern "C" void kernel_launch(void* const* d_in, const int* in_sizes, int n_in,
                              void* d_out, int out_size)
{
    const float* x      = (const float*)d_in[0];
    const float* w_qkv  = (const float*)d_in[1];
    const float* w_dw   = (const float*)d_in[2];
    const float* w_proj = (const float*)d_in[3];
    const float* temp   = (const float*)d_in[4];
    const float* a1     = (const float*)d_in[5];
    const float* a2     = (const float*)d_in[6];
    const float* a3     = (const float*)d_in[7];
    const float* a4     = (const float*)d_in[8];
    float* out = (float*)d_out;

    float *qkv, *dwb, *cpart, *cnp, *ccoef;
    __nv_bfloat16 *xth, *xtl, *wqh, *wql, *wph, *wpl;
    cudaGetSymbolAddress((void**)&qkv,   g_qkv);
    cudaGetSymbolAddress((void**)&dwb,   g_dw);
    cudaGetSymbolAddress((void**)&cpart, g_cpart);
    cudaGetSymbolAddress((void**)&cnp,   g_cnp);
    cudaGetSymbolAddress((void**)&ccoef, g_ccoef);
    cudaGetSymbolAddress((void**)&xth,   g_xth);
    cudaGetSymbolAddress((void**)&xtl,   g_xtl);
    cudaGetSymbolAddress((void**)&wqh,   g_wqh);
    cudaGetSymbolAddress((void**)&wql,   g_wql);
    cudaGetSymbolAddress((void**)&wph,   g_wph);
    cudaGetSymbolAddress((void**)&wpl,   g_wpl);

    const int spatial_smem =
        (64 * SQ_STR * 2 + 48 * SAT_STR + 64 * SAT_STR + 64 + 64 + 64 * 4) * 4;
    const int gemm_smem = 2 * 4 * AS * 2;   // 81920 B
    cudaFuncSetAttribute(spatial_kernel, cudaFuncAttributeMaxDynamicSharedMemorySize, 65536);
    cudaFuncSetAttribute(hmma_gemm, cudaFuncAttributeMaxDynamicSharedMemorySize, gemm_smem);

    // 0) weight splits + X transpose/split
    convert_w<<<(NQKV * NCH + 255) / 256, 256>>>(w_qkv, wqh, wql, NQKV * NCH);
    convert_w<<<(NCH * NCH + 255) / 256, 256>>>(w_proj, wph, wpl, NCH * NCH);
    transpose_split<<<dim3(P_PIX / 32, GK / 32, 2), 256>>>(x, xth, xtl);
    // 1) qkv = 1x1 conv via split-bf16 HMMA (M=1152)
    hmma_gemm<<<dim3(P_PIX / 128, NQKV / 128, 2), 256, gemm_smem>>>(wqh, wql, xth, xtl, qkv, NQKV);
    // 2) depthwise 3x3 (2x4 tile per thread)
    dwconv_kernel<<<(2 * NQKV * P_PIX / 8) / 256, 256>>>(qkv, w_dw, dwb);
    // 3) cattn split-K partials + fused row norms (f32x2)
    cattn_kernel<<<dim3(CSPLIT, 16), 256>>>(dwb, cpart, cnp);
    // 4) channel softmax coefficients (reduces norms inline)
    chan_coef_kernel<<<96, 256>>>(cpart, cnp, temp, a1, a2, a3, a4, ccoef);
    // 5) fused spatial + channel output, emits proj input bf16 hi/lo transposed
    spatial_kernel<<<dim3(512, HEADS), 256, spatial_smem>>>(
        dwb, ccoef, temp, a1, a2, a3, a4, xth, xtl);
    // 6) proj GEMM (M=384) -> d_out
    hmma_gemm<<<dim3(P_PIX / 128, NCH / 128, 2), 256, gemm_smem>>>(wph, wpl, xth, xtl, out, NCH);
}

// round 17
// speedup vs baseline: 1.1877x; 1.0693x over previous
#include <cuda_runtime.h>
#include <cuda_bf16.h>
#include <math.h>
#include <cstdint>

#define P_PIX 16384   // 128*128
#define NCH   384
#define NQKV  1152
#define HEADS 8
#define CH    48      // per-head channels
#define NWIN  64      // tokens per 8x8 window
#define CSPLIT 32     // cattn K splits
#define GK    384     // GEMM K (both gemms)
#define BK    32      // K chunk (cp.async stage)
#define NKC   (GK / BK)   // 12 chunks
#define A_STR 40      // smem row stride (bf16), 80B: conflict-free ldmatrix
#define AS    (128 * A_STR)   // elems per array tile

typedef unsigned long long u64t;

__device__ __forceinline__ u64t dup_f32(float a) {
    u64t r; asm("mov.b64 %0, {%1, %1};" : "=l"(r) : "f"(a)); return r;
}
__device__ __forceinline__ void ffma2(u64t& acc, u64t a, u64t b) {
    asm("fma.rn.f32x2 %0, %1, %2, %0;" : "+l"(acc) : "l"(a), "l"(b));
}
__device__ __forceinline__ float pair_sum(u64t v) {
    float lo, hi; asm("mov.b64 {%0, %1}, %2;" : "=f"(lo), "=f"(hi) : "l"(v)); return lo + hi;
}
__device__ __forceinline__ uint32_t smem_u32(const void* p) {
    uint32_t a;
    asm("{ .reg .u64 t; cvta.to.shared.u64 t, %1; cvt.u32.u64 %0, t; }" : "=r"(a) : "l"(p));
    return a;
}
__device__ __forceinline__ void ldsm_x4(uint32_t* r, uint32_t addr) {
    asm volatile("ldmatrix.sync.aligned.m8n8.x4.shared.b16 {%0,%1,%2,%3}, [%4];"
                 : "=r"(r[0]), "=r"(r[1]), "=r"(r[2]), "=r"(r[3]) : "r"(addr));
}
__device__ __forceinline__ void ldsm_x2(uint32_t* r, uint32_t addr) {
    asm volatile("ldmatrix.sync.aligned.m8n8.x2.shared.b16 {%0,%1}, [%2];"
                 : "=r"(r[0]), "=r"(r[1]) : "r"(addr));
}
__device__ __forceinline__ void mma_bf16(float* c, const uint32_t* a, const uint32_t* b) {
    asm volatile("mma.sync.aligned.m16n8k16.row.col.f32.bf16.bf16.f32 "
                 "{%0,%1,%2,%3}, {%4,%5,%6,%7}, {%8,%9}, {%0,%1,%2,%3};"
                 : "+f"(c[0]), "+f"(c[1]), "+f"(c[2]), "+f"(c[3])
                 : "r"(a[0]), "r"(a[1]), "r"(a[2]), "r"(a[3]), "r"(b[0]), "r"(b[1]));
}
__device__ __forceinline__ void cp_async16(uint32_t saddr, const void* g) {
    asm volatile("cp.async.cg.shared.global [%0], [%1], 16;" :: "r"(saddr), "l"(g));
}
#define CP_COMMIT() asm volatile("cp.async.commit_group;" ::: "memory")
#define CP_WAIT1()  asm volatile("cp.async.wait_group 1;" ::: "memory")
#define CP_WAIT0()  asm volatile("cp.async.wait_group 0;" ::: "memory")

// ---------------- scratch (device globals; no allocs allowed) ----------------
__device__ float g_qkv[2ll * NQKV * P_PIX];
__device__ float g_dw [2ll * NQKV * P_PIX];
__device__ float g_cpart[CSPLIT * 16 * CH * CH];
__device__ float g_cnp[CSPLIT * 16 * 96];
__device__ float g_ccoef[16 * CH * CH];
__device__ __nv_bfloat16 g_xth[2ll * P_PIX * GK];
__device__ __nv_bfloat16 g_xtl[2ll * P_PIX * GK];
__device__ __nv_bfloat16 g_wqh[NQKV * NCH];
__device__ __nv_bfloat16 g_wql[NQKV * NCH];
__device__ __nv_bfloat16 g_wph[NCH * NCH];
__device__ __nv_bfloat16 g_wpl[NCH * NCH];

// ---------------- weight split fp32 -> bf16 hi/lo ----------------
__global__ __launch_bounds__(256) void convert_w(
    const float* __restrict__ W, __nv_bfloat16* __restrict__ Wh,
    __nv_bfloat16* __restrict__ Wl, int n)
{
    int i = blockIdx.x * 256 + threadIdx.x;
    if (i >= n) return;
    float v = W[i];
    __nv_bfloat16 hi = __float2bfloat16(v);
    Wh[i] = hi;
    Wl[i] = __float2bfloat16(v - __bfloat162float(hi));
}

// ------- transpose+split: X fp32 [b][K=384][16384] -> T bf16 [b][16384][384] --
__global__ __launch_bounds__(256) void transpose_split(
    const float* __restrict__ X, __nv_bfloat16* __restrict__ Th,
    __nv_bfloat16* __restrict__ Tl)
{
    __shared__ float s[32][33];
    const int b  = blockIdx.z;
    const int p0 = blockIdx.x * 32;
    const int k0 = blockIdx.y * 32;
    const int tid = threadIdx.x;
    const int tx = tid & 31, ty = tid >> 5;
    const float* Xb = X + ((size_t)b * GK + k0) * P_PIX + p0;
#pragma unroll
    for (int i = 0; i < 4; i++)
        s[ty + 8 * i][tx] = Xb[(size_t)(ty + 8 * i) * P_PIX + tx];
    __syncthreads();
    const int row = tid >> 3;
    const int kk = (tid & 7) * 4;
    __nv_bfloat16 hv[4], lv[4];
#pragma unroll
    for (int j = 0; j < 4; j++) {
        float v = s[kk + j][row];
        hv[j] = __float2bfloat16(v);
        lv[j] = __float2bfloat16(v - __bfloat162float(hv[j]));
    }
    size_t ob = ((size_t)b * P_PIX + p0 + row) * GK + k0 + kk;
    *reinterpret_cast<__nv_bfloat162*>(&Th[ob])     = *reinterpret_cast<__nv_bfloat162*>(&hv[0]);
    *reinterpret_cast<__nv_bfloat162*>(&Th[ob + 2]) = *reinterpret_cast<__nv_bfloat162*>(&hv[2]);
    *reinterpret_cast<__nv_bfloat162*>(&Tl[ob])     = *reinterpret_cast<__nv_bfloat162*>(&lv[0]);
    *reinterpret_cast<__nv_bfloat162*>(&Tl[ob + 2]) = *reinterpret_cast<__nv_bfloat162*>(&lv[2]);
}

// ------------- split-bf16 HMMA GEMM, cp.async double-buffered (R9 config) ----
__global__ __launch_bounds__(256, 2) void hmma_gemm(
    const __nv_bfloat16* __restrict__ Wh, const __nv_bfloat16* __restrict__ Wl,
    const __nv_bfloat16* __restrict__ Th, const __nv_bfloat16* __restrict__ Tl,
    float* __restrict__ Y, int M)
{
    extern __shared__ __nv_bfloat16 sm[];
    const uint32_t sm32 = smem_u32(sm);

    const int tid = threadIdx.x;
    const int wid = tid >> 5, lane = tid & 31;
    const int wr = wid >> 2;
    const int wc = wid & 3;
    const int b  = blockIdx.z;
    const int m0 = blockIdx.y * 128;
    const int p0 = blockIdx.x * 128;

    const __nv_bfloat16* gA[4];
    gA[0] = Wh + (size_t)m0 * GK;
    gA[1] = Wl + (size_t)m0 * GK;
    gA[2] = Th + ((size_t)b * P_PIX + p0) * GK;
    gA[3] = Tl + ((size_t)b * P_PIX + p0) * GK;

    float acc[4][4][4];
#pragma unroll
    for (int i = 0; i < 4; i++)
#pragma unroll
        for (int j = 0; j < 4; j++)
#pragma unroll
            for (int r = 0; r < 4; r++) acc[i][j][r] = 0.f;

    auto issue = [&](int chunk, int buf) {
        const int kb = chunk * BK;
        const uint32_t bufb = sm32 + (uint32_t)buf * 4 * AS * 2;
#pragma unroll
        for (int i = 0; i < 2; i++) {
            int idx = tid + i * 256;
            int row = idx >> 2, c8 = (idx & 3) * 8;
            size_t go = (size_t)row * GK + kb + c8;
            uint32_t so = bufb + (uint32_t)(row * A_STR + c8) * 2;
#pragma unroll
            for (int a = 0; a < 4; a++)
                cp_async16(so + (uint32_t)a * AS * 2, gA[a] + go);
        }
        CP_COMMIT();
    };

    issue(0, 0);
    issue(1, 1);

    for (int c = 0; c < NKC; c++) {
        if (c + 1 < NKC) CP_WAIT1(); else CP_WAIT0();
        __syncthreads();
        const uint32_t bufb = sm32 + (uint32_t)(c & 1) * 4 * AS * 2;
        const uint32_t sAh32 = bufb;
        const uint32_t sAl32 = bufb + AS * 2;
        const uint32_t sBh32 = bufb + 2 * AS * 2;
        const uint32_t sBl32 = bufb + 3 * AS * 2;

#pragma unroll
        for (int ks = 0; ks < BK / 16; ks++) {
            const int k0 = ks * 16;
            const int nrow = wc * 32 + (lane & 7);
            const int ncol = k0 + ((lane >> 3) & 1) * 8;
            const int arow = wr * 64 + (lane & 15);
            const int acol = k0 + (lane >> 4) * 8;

            uint32_t bH[4][2], aH[4][4];
#pragma unroll
            for (int nt = 0; nt < 4; nt++)
                ldsm_x2(bH[nt], sBh32 + (uint32_t)((nrow + nt * 8) * A_STR + ncol) * 2);
#pragma unroll
            for (int mt = 0; mt < 4; mt++)
                ldsm_x4(aH[mt], sAh32 + (uint32_t)((arow + mt * 16) * A_STR + acol) * 2);
#pragma unroll
            for (int mt = 0; mt < 4; mt++)
#pragma unroll
                for (int nt = 0; nt < 4; nt++)
                    mma_bf16(acc[mt][nt], aH[mt], bH[nt]);
            uint32_t bL[4][2];
#pragma unroll
            for (int nt = 0; nt < 4; nt++)
                ldsm_x2(bL[nt], sBl32 + (uint32_t)((nrow + nt * 8) * A_STR + ncol) * 2);
#pragma unroll
            for (int mt = 0; mt < 4; mt++)
#pragma unroll
                for (int nt = 0; nt < 4; nt++)
                    mma_bf16(acc[mt][nt], aH[mt], bL[nt]);
            uint32_t aL[4][4];
#pragma unroll
            for (int mt = 0; mt < 4; mt++)
                ldsm_x4(aL[mt], sAl32 + (uint32_t)((arow + mt * 16) * A_STR + acol) * 2);
#pragma unroll
            for (int mt = 0; mt < 4; mt++)
#pragma unroll
                for (int nt = 0; nt < 4; nt++)
                    mma_bf16(acc[mt][nt], aL[mt], bH[nt]);
        }
        __syncthreads();
        if (c + 2 < NKC) issue(c + 2, c & 1);
    }

    const int tq = lane >> 2;
    const int tr4 = lane & 3;
#pragma unroll
    for (int mt = 0; mt < 4; mt++) {
#pragma unroll
        for (int nt = 0; nt < 4; nt++) {
            int m  = m0 + wr * 64 + mt * 16 + tq;
            int p  = p0 + wc * 32 + nt * 8 + tr4 * 2;
            float* y0 = &Y[((size_t)b * M + m) * P_PIX + p];
            *reinterpret_cast<float2*>(y0) = make_float2(acc[mt][nt][0], acc[mt][nt][1]);
            float* y1 = &Y[((size_t)b * M + m + 8) * P_PIX + p];
            *reinterpret_cast<float2*>(y1) = make_float2(acc[mt][nt][2], acc[mt][nt][3]);
        }
    }
}

// ---------- depthwise 3x3, pad 1, 2x4 tile; channel-range variant -----------
__global__ __launch_bounds__(256) void dwconv_kernel(
    const float* __restrict__ in, const float* __restrict__ Wd, float* __restrict__ out,
    int chBase, int chCnt)
{
    int gid = blockIdx.x * 256 + threadIdx.x;
    int grp = gid & 2047;
    int bc2 = gid >> 11;             // 0 .. 2*chCnt
    int b   = bc2 / chCnt;
    int ch  = chBase + (bc2 - b * chCnt);
    size_t bc = (size_t)b * NQKV + ch;
    int x0 = (grp & 31) * 4, y0 = (grp >> 5) * 2;
    const float* ip = in + bc * P_PIX;
    const float* w  = Wd + ch * 9;
    float o0[4] = {0.f, 0.f, 0.f, 0.f};
    float o1[4] = {0.f, 0.f, 0.f, 0.f};
#pragma unroll
    for (int r = 0; r < 4; r++) {
        int yy = y0 - 1 + r;
        if ((unsigned)yy >= 128u) continue;
        const float* rp = ip + yy * 128;
        float v[6];
#pragma unroll
        for (int t = 0; t < 6; t++) {
            int xx = x0 - 1 + t;
            v[t] = ((unsigned)xx < 128u) ? rp[xx] : 0.f;
        }
#pragma unroll
        for (int dx = 0; dx < 3; dx++) {
            if (r < 3) {
                float wv = w[r * 3 + dx];
#pragma unroll
                for (int i = 0; i < 4; i++) o0[i] = fmaf(wv, v[dx + i], o0[i]);
            }
            if (r >= 1) {
                float wv = w[(r - 1) * 3 + dx];
#pragma unroll
                for (int i = 0; i < 4; i++) o1[i] = fmaf(wv, v[dx + i], o1[i]);
            }
        }
    }
    float* ob = out + bc * P_PIX + y0 * 128 + x0;
    *reinterpret_cast<float4*>(ob)       = make_float4(o0[0], o0[1], o0[2], o0[3]);
    *reinterpret_cast<float4*>(ob + 128) = make_float4(o1[0], o1[1], o1[2], o1[3]);
}

// ------ cattn raw dots + fused row sumsq, split-K partials, f32x2 -----------
__global__ __launch_bounds__(256) void cattn_kernel(
    const float* __restrict__ dw, float* __restrict__ part, float* __restrict__ cnp)
{
    const int bh = blockIdx.y;
    const int b = bh >> 3, h = bh & 7;
    const int kbase = blockIdx.x * (P_PIX / CSPLIT);
    const float* qb = dw + ((size_t)b * NQKV + h * CH) * P_PIX;
    const float* kb = dw + ((size_t)b * NQKV + NCH + h * CH) * P_PIX;

    __shared__ float sq[CH][66];
    __shared__ float sk[CH][66];

    const int tid = threadIdx.x;
    const int ti = tid >> 4, tj = tid & 15;
    const int i0 = ti * 3, j0 = tj * 3;

    u64t acc2[3][3];
#pragma unroll
    for (int r = 0; r < 3; r++)
#pragma unroll
        for (int c = 0; c < 3; c++) acc2[r][c] = 0ull;
    float nrm = 0.f;

    for (int kc = 0; kc < P_PIX / CSPLIT; kc += 64) {
        const int kpos = kbase + kc;
        for (int e = tid; e < CH * 16; e += 256) {
            int r = e >> 4, c4 = (e & 15) * 4;
            float4 vq = *reinterpret_cast<const float4*>(&qb[(size_t)r * P_PIX + kpos + c4]);
            float4 vk = *reinterpret_cast<const float4*>(&kb[(size_t)r * P_PIX + kpos + c4]);
            sq[r][c4] = vq.x; sq[r][c4+1] = vq.y; sq[r][c4+2] = vq.z; sq[r][c4+3] = vq.w;
            sk[r][c4] = vk.x; sk[r][c4+1] = vk.y; sk[r][c4+2] = vk.z; sk[r][c4+3] = vk.w;
        }
        __syncthreads();
        if (tid < 96) {
            const float* rowp = (tid < 48) ? &sq[tid][0] : &sk[tid - 48][0];
#pragma unroll 16
            for (int c = 0; c < 64; c++) nrm = fmaf(rowp[c], rowp[c], nrm);
        }
        const u64t* a0p = reinterpret_cast<const u64t*>(&sq[i0][0]);
        const u64t* a1p = reinterpret_cast<const u64t*>(&sq[i0 + 1][0]);
        const u64t* a2p = reinterpret_cast<const u64t*>(&sq[i0 + 2][0]);
        const u64t* b0p = reinterpret_cast<const u64t*>(&sk[j0][0]);
        const u64t* b1p = reinterpret_cast<const u64t*>(&sk[j0 + 1][0]);
        const u64t* b2p = reinterpret_cast<const u64t*>(&sk[j0 + 2][0]);
#pragma unroll 8
        for (int kk = 0; kk < 32; kk++) {
            u64t a0 = a0p[kk], a1 = a1p[kk], a2 = a2p[kk];
            u64t b0 = b0p[kk], b1 = b1p[kk], b2 = b2p[kk];
            ffma2(acc2[0][0], a0, b0);
            ffma2(acc2[0][1], a0, b1);
            ffma2(acc2[0][2], a0, b2);
            ffma2(acc2[1][0], a1, b0);
            ffma2(acc2[1][1], a1, b1);
            ffma2(acc2[1][2], a1, b2);
            ffma2(acc2[2][0], a2, b0);
            ffma2(acc2[2][1], a2, b1);
            ffma2(acc2[2][2], a2, b2);
        }
        __syncthreads();
    }
    float* pr = &part[((size_t)blockIdx.x * 16 + bh) * (CH * CH)];
#pragma unroll
    for (int r = 0; r < 3; r++)
#pragma unroll
        for (int c = 0; c < 3; c++)
            pr[(i0 + r) * CH + (j0 + c)] = pair_sum(acc2[r][c]);
    if (tid < 96)
        cnp[((size_t)blockIdx.x * 16 + bh) * 96 + tid] = nrm;
}

// ------- channel branch: combined top-k softmax coefficients ----------------
__global__ __launch_bounds__(256) void chan_coef_kernel(
    const float* __restrict__ part, const float* __restrict__ cnp,
    const float* __restrict__ temp,
    const float* __restrict__ w1p, const float* __restrict__ w2p,
    const float* __restrict__ w3p, const float* __restrict__ w4p,
    float* __restrict__ coef)
{
    const int warp = threadIdx.x >> 5, ln = threadIdx.x & 31;
    const int row = blockIdx.x * 8 + warp;
    const int bh = row / CH, i = row % CH;
    const int h = bh & 7;
    const float t = temp[h];
    const int KT[4] = {23, 31, 35, 37};
    float wts[4] = {w1p[0], w2p[0], w3p[0], w4p[0]};

    __shared__ float sa[8][CH];
    __shared__ float sth[8][4];

    int j0 = ln, j1 = ln + 32;
    float d0 = 0.f, d1 = 0.f, sqi = 0.f, skk0 = 0.f, skk1 = 0.f;
    for (int s = 0; s < CSPLIT; s++) {
        const float* pr = part + ((size_t)s * 16 + bh) * (CH * CH) + i * CH;
        const float* np = cnp + ((size_t)s * 16 + bh) * 96;
        d0 += pr[j0];
        sqi += np[i];
        skk0 += np[48 + j0];
        if (j1 < CH) { d1 += pr[j1]; skk1 += np[48 + j1]; }
    }
    float inq = 1.f / fmaxf(sqrtf(sqi), 1e-12f);
    float nk0 = fmaxf(sqrtf(skk0), 1e-12f);
    float nk1 = fmaxf(sqrtf(skk1), 1e-12f);
    float a0 = d0 * inq / nk0 * t;
    float a1 = (j1 < CH) ? d1 * inq / nk1 * t : -INFINITY;
    sa[warp][j0] = a0;
    if (j1 < CH) sa[warp][j1] = a1;
    __syncwarp();

    int r0 = 0, r1 = 0;
    for (int q = 0; q < CH; q++) {
        float aq = sa[warp][q];
        r0 += (aq > a0) || (aq == a0 && q < j0);
        if (j1 < CH) r1 += (aq > a1) || (aq == a1 && q < j1);
    }
#pragma unroll
    for (int kx = 0; kx < 4; kx++) {
        if (r0 == KT[kx]) sth[warp][kx] = a0;
        if (j1 < CH && r1 == KT[kx]) sth[warp][kx] = a1;
    }
    __syncwarp();

    float m = fmaxf(a0, a1);
#pragma unroll
    for (int o = 16; o; o >>= 1) m = fmaxf(m, __shfl_xor_sync(0xffffffffu, m, o));
    float e0 = expf(a0 - m);
    float e1 = (j1 < CH) ? expf(a1 - m) : 0.f;

    float th4[4], z[4];
#pragma unroll
    for (int kx = 0; kx < 4; kx++) {
        th4[kx] = sth[warp][kx];
        z[kx] = (a0 >= th4[kx] ? e0 : 0.f) + ((j1 < CH && a1 >= th4[kx]) ? e1 : 0.f);
    }
#pragma unroll
    for (int o = 16; o; o >>= 1) {
        z[0] += __shfl_xor_sync(0xffffffffu, z[0], o);
        z[1] += __shfl_xor_sync(0xffffffffu, z[1], o);
        z[2] += __shfl_xor_sync(0xffffffffu, z[2], o);
        z[3] += __shfl_xor_sync(0xffffffffu, z[3], o);
    }
    float c0 = 0.f, c1 = 0.f;
#pragma unroll
    for (int kx = 0; kx < 4; kx++) {
        float f = wts[kx] / z[kx];
        if (a0 >= th4[kx]) c0 += f;
        if (j1 < CH && a1 >= th4[kx]) c1 += f;
    }
    coef[row * CH + j0] = e0 * c0;
    if (j1 < CH) coef[row * CH + j1] = e1 * c1;
}

// ---- fused spatial attention + channel output + transpose/split emit -------
#define SQ_STR 50
#define SAT_STR 66
#define CF_STR 50
#define VO_STR 66
__global__ __launch_bounds__(256) void spatial_kernel(
    const float* __restrict__ dw, const float* __restrict__ coef,
    const float* __restrict__ temp,
    const float* __restrict__ w1p, const float* __restrict__ w2p,
    const float* __restrict__ w3p, const float* __restrict__ w4p,
    __nv_bfloat16* __restrict__ Th, __nv_bfloat16* __restrict__ Tl)
{
    extern __shared__ float smemf[];
    float* sq  = smemf;                      // 64*50 q  (later: coefT 48*50)
    float* sk2 = sq  + 64 * SQ_STR;          // 64*50 k  (later: vout 48*66)
    float* svT = sk2 + 64 * SQ_STR;          // 48*66
    float* sat = svT + 48 * SAT_STR;         // 64*66 scores (later: obuf 48*66)
    float* nq  = sat + 64 * SAT_STR;         // 64
    float* nk  = nq  + 64;                   // 64
    float* sth = nk  + 64;                   // 64*4

    const int win = blockIdx.x;
    const int head = blockIdx.y;
    const int b = win >> 8, wy = (win >> 4) & 15, wx = win & 15;
    const int bh = b * 8 + head;
    const int tid = threadIdx.x;
    const int ti = tid >> 4, tj = tid & 15;
    const int pbase = wy * 1024 + wx * 64;

    const size_t base = ((size_t)b * NQKV + head * CH) * P_PIX + (size_t)(wy * 8) * 128 + wx * 8;
    const float* vglob = dw + ((size_t)b * NQKV + 2 * NCH + head * CH) * P_PIX;

    for (int e = tid; e < NWIN * CH; e += 256) {
        int c = e >> 6, n = e & 63;
        int iy = n >> 3, ix = n & 7;
        size_t off = (size_t)c * P_PIX + iy * 128 + ix;
        sq [n * SQ_STR + c] = dw[base + off];
        sk2[n * SQ_STR + c] = dw[base + (size_t)NCH * P_PIX + off];
        svT[c * SAT_STR + n] = dw[base + (size_t)(2 * NCH) * P_PIX + off];
    }
    __syncthreads();

    if (tid < 128) {
        int n = tid & 63;
        const float* src = (tid < 64) ? sq : sk2;
        float s = 0.f;
#pragma unroll
        for (int c = 0; c < CH; c++) { float v = src[n * SQ_STR + c]; s = fmaf(v, v, s); }
        float nn = fmaxf(sqrtf(s), 1e-12f);
        if (tid < 64) nq[n] = nn; else nk[n] = nn;
    }
    __syncthreads();

    const float t = temp[wx & 7];
    {
        u64t accq2[4][4];
#pragma unroll
        for (int i = 0; i < 4; i++)
#pragma unroll
            for (int j = 0; j < 4; j++) accq2[i][j] = 0ull;
        const u64t* qp[4];
        const u64t* kp[4];
#pragma unroll
        for (int i = 0; i < 4; i++) qp[i] = reinterpret_cast<const u64t*>(&sq[(ti + 16 * i) * SQ_STR]);
#pragma unroll
        for (int j = 0; j < 4; j++) kp[j] = reinterpret_cast<const u64t*>(&sk2[(tj + 16 * j) * SQ_STR]);
#pragma unroll 4
        for (int c2 = 0; c2 < CH / 2; c2++) {
            u64t qv[4], kv[4];
#pragma unroll
            for (int i = 0; i < 4; i++) qv[i] = qp[i][c2];
#pragma unroll
            for (int j = 0; j < 4; j++) kv[j] = kp[j][c2];
#pragma unroll
            for (int i = 0; i < 4; i++)
#pragma unroll
                for (int j = 0; j < 4; j++)
                    ffma2(accq2[i][j], qv[i], kv[j]);
        }
        float qn[4], kn[4];
#pragma unroll
        for (int i = 0; i < 4; i++) qn[i] = nq[ti + 16 * i];
#pragma unroll
        for (int j = 0; j < 4; j++) kn[j] = nk[tj + 16 * j];
#pragma unroll
        for (int i = 0; i < 4; i++)
#pragma unroll
            for (int j = 0; j < 4; j++)
                sat[(ti + 16 * i) * SAT_STR + tj + 16 * j] =
                    pair_sum(accq2[i][j]) / (qn[i] * kn[j]) * t;
    }
    __syncthreads();   // sq, sk2 now dead

    float* coefT = sq;
    float* vout  = sk2;
    {
        const float* cf = coef + bh * CH * CH;
        for (int e = tid; e < CH * CH; e += 256) {
            int j = e / CH, c = e % CH;
            coefT[j * CF_STR + c] = cf[c * CH + j];
        }
        for (int e = tid; e < CH * NWIN; e += 256) {
            int c = e >> 6, n = e & 63;
            vout[c * VO_STR + n] = vglob[(size_t)c * P_PIX + pbase + n];
        }
    }

    const int warp = tid >> 5, ln = tid & 31;
    const int KT[4] = {31, 41, 47, 50};
    float wts[4] = {w1p[0], w2p[0], w3p[0], w4p[0]};

    for (int rr = 0; rr < 8; rr++) {
        int n = warp * 8 + rr;
        float a0 = sat[n * SAT_STR + ln];
        float a1 = sat[n * SAT_STR + ln + 32];
        // shfl-based all-pairs rank (row values live in warp registers)
        int r0 = 0, r1 = 0;
#pragma unroll 8
        for (int s = 0; s < 32; s++) {
            float b0 = __shfl_sync(0xffffffffu, a0, s);
            float b1 = __shfl_sync(0xffffffffu, a1, s);
            r0 += (b0 > a0) || (b0 == a0 && s < ln);   // vs idx s
            r0 += (b1 > a0);                            // vs idx s+32 (s+32<ln impossible)
            r1 += (b0 >= a1);                           // vs idx s (s<ln+32 always)
            r1 += (b1 > a1) || (b1 == a1 && s < ln);   // vs idx s+32
        }
#pragma unroll
        for (int kx = 0; kx < 4; kx++) {
            if (r0 == KT[kx]) sth[n * 4 + kx] = a0;
            if (r1 == KT[kx]) sth[n * 4 + kx] = a1;
        }
        __syncwarp();

        float m = fmaxf(a0, a1);
#pragma unroll
        for (int o = 16; o; o >>= 1) m = fmaxf(m, __shfl_xor_sync(0xffffffffu, m, o));
        float e0 = expf(a0 - m), e1 = expf(a1 - m);

        float th4[4], z[4];
#pragma unroll
        for (int kx = 0; kx < 4; kx++) {
            th4[kx] = sth[n * 4 + kx];
            z[kx] = (a0 >= th4[kx] ? e0 : 0.f) + (a1 >= th4[kx] ? e1 : 0.f);
        }
#pragma unroll
        for (int o = 16; o; o >>= 1) {
            z[0] += __shfl_xor_sync(0xffffffffu, z[0], o);
            z[1] += __shfl_xor_sync(0xffffffffu, z[1], o);
            z[2] += __shfl_xor_sync(0xffffffffu, z[2], o);
            z[3] += __shfl_xor_sync(0xffffffffu, z[3], o);
        }
        float c0 = 0.f, c1 = 0.f;
#pragma unroll
        for (int kx = 0; kx < 4; kx++) {
            float f = wts[kx] / z[kx];
            if (a0 >= th4[kx]) c0 += f;
            if (a1 >= th4[kx]) c1 += f;
        }
        __syncwarp();
        sat[n * SAT_STR + ln]      = e0 * c0;
        sat[n * SAT_STR + ln + 32] = e1 * c1;
        __syncwarp();
    }
    __syncthreads();

    float res[3][4];
    {
        u64t acca2[3][4];
#pragma unroll
        for (int i = 0; i < 3; i++)
#pragma unroll
            for (int j = 0; j < 4; j++) acca2[i][j] = 0ull;
        const u64t* ap[4];
        const u64t* vp[3];
#pragma unroll
        for (int j = 0; j < 4; j++) ap[j] = reinterpret_cast<const u64t*>(&sat[(ti + 16 * j) * SAT_STR]);
#pragma unroll
        for (int i = 0; i < 3; i++) vp[i] = reinterpret_cast<const u64t*>(&svT[(tj + 16 * i) * SAT_STR]);
#pragma unroll 4
        for (int m2 = 0; m2 < NWIN / 2; m2++) {
            u64t av[4], vv[3];
#pragma unroll
            for (int j = 0; j < 4; j++) av[j] = ap[j][m2];
#pragma unroll
            for (int i = 0; i < 3; i++) vv[i] = vp[i][m2];
#pragma unroll
            for (int i = 0; i < 3; i++)
#pragma unroll
                for (int j = 0; j < 4; j++)
                    ffma2(acca2[i][j], av[j], vv[i]);
        }
        float accc[3][4];
#pragma unroll
        for (int i = 0; i < 3; i++)
#pragma unroll
            for (int j = 0; j < 4; j++) accc[i][j] = 0.f;
#pragma unroll 4
        for (int j = 0; j < CH; j++) {
            float cfv[3], vv[4];
#pragma unroll
            for (int i = 0; i < 3; i++) cfv[i] = coefT[j * CF_STR + tj + 16 * i];
#pragma unroll
            for (int jj = 0; jj < 4; jj++) vv[jj] = vout[j * VO_STR + ti + 16 * jj];
#pragma unroll
            for (int i = 0; i < 3; i++)
#pragma unroll
                for (int jj = 0; jj < 4; jj++)
                    accc[i][jj] = fmaf(cfv[i], vv[jj], accc[i][jj]);
        }
#pragma unroll
        for (int i = 0; i < 3; i++)
#pragma unroll
            for (int j = 0; j < 4; j++)
                res[i][j] = pair_sum(acca2[i][j]) + accc[i][j];
    }
    __syncthreads();

    float* obuf = sat;
#pragma unroll
    for (int i = 0; i < 3; i++)
#pragma unroll
        for (int j = 0; j < 4; j++)
            obuf[(tj + 16 * i) * SAT_STR + ti + 16 * j] = res[i][j];
    __syncthreads();

    {
#pragma unroll
        for (int o = 0; o < 6; o++) {
            int e = tid + o * 256;
            int n = e / 24, c = (e % 24) * 2;
            float v0 = obuf[c * SAT_STR + n];
            float v1 = obuf[(c + 1) * SAT_STR + n];
            __nv_bfloat16 h0 = __float2bfloat16(v0);
            __nv_bfloat16 h1 = __float2bfloat16(v1);
            __nv_bfloat16 l0 = __float2bfloat16(v0 - __bfloat162float(h0));
            __nv_bfloat16 l1 = __float2bfloat16(v1 - __bfloat162float(h1));
            size_t ob = ((size_t)b * P_PIX + pbase + n) * GK + head * CH + c;
            *reinterpret_cast<__nv_bfloat162*>(&Th[ob]) = __nv_bfloat162(h0, h1);
            *reinterpret_cast<__nv_bfloat162*>(&Tl[ob]) = __nv_bfloat162(l0, l1);
        }
    }
}

// ---------------- host launcher ----------------
extern "C" void kernel_launch(void* const* d_in, const int* in_sizes, int n_in,
                              void* d_out, int out_size)
{
    const float* x      = (const float*)d_in[0];
    const float* w_qkv  = (const float*)d_in[1];
    const float* w_dw   = (const float*)d_in[2];
    const float* w_proj = (const float*)d_in[3];
    const float* temp   = (const float*)d_in[4];
    const float* a1     = (const float*)d_in[5];
    const float* a2     = (const float*)d_in[6];
    const float* a3     = (const float*)d_in[7];
    const float* a4     = (const float*)d_in[8];
    float* out = (float*)d_out;

    float *qkv, *dwb, *cpart, *cnp, *ccoef;
    __nv_bfloat16 *xth, *xtl, *wqh, *wql, *wph, *wpl;
    cudaGetSymbolAddress((void**)&qkv,   g_qkv);
    cudaGetSymbolAddress((void**)&dwb,   g_dw);
    cudaGetSymbolAddress((void**)&cpart, g_cpart);
    cudaGetSymbolAddress((void**)&cnp,   g_cnp);
    cudaGetSymbolAddress((void**)&ccoef, g_ccoef);
    cudaGetSymbolAddress((void**)&xth,   g_xth);
    cudaGetSymbolAddress((void**)&xtl,   g_xtl);
    cudaGetSymbolAddress((void**)&wqh,   g_wqh);
    cudaGetSymbolAddress((void**)&wql,   g_wql);
    cudaGetSymbolAddress((void**)&wph,   g_wph);
    cudaGetSymbolAddress((void**)&wpl,   g_wpl);

    // side stream + events for capture fork (created once; host objects, not device mem)
    static cudaStream_t s2 = nullptr;
    static cudaEvent_t evFork = nullptr, evJoin = nullptr;
    if (!s2) {
        cudaStreamCreateWithFlags(&s2, cudaStreamNonBlocking);
        cudaEventCreateWithFlags(&evFork, cudaEventDisableTiming);
        cudaEventCreateWithFlags(&evJoin, cudaEventDisableTiming);
    }

    const int spatial_smem =
        (64 * SQ_STR * 2 + 48 * SAT_STR + 64 * SAT_STR + 64 + 64 + 64 * 4) * 4;
    const int gemm_smem = 2 * 4 * AS * 2;   // 81920 B
    cudaFuncSetAttribute(spatial_kernel, cudaFuncAttributeMaxDynamicSharedMemorySize, 65536);
    cudaFuncSetAttribute(hmma_gemm, cudaFuncAttributeMaxDynamicSharedMemorySize, gemm_smem);

    // 0) weight splits + X transpose/split
    convert_w<<<(NQKV * NCH + 255) / 256, 256>>>(w_qkv, wqh, wql, NQKV * NCH);
    convert_w<<<(NCH * NCH + 255) / 256, 256>>>(w_proj, wph, wpl, NCH * NCH);
    transpose_split<<<dim3(P_PIX / 32, GK / 32, 2), 256>>>(x, xth, xtl);
    // 1) qkv = 1x1 conv via split-bf16 HMMA (M=1152)
    hmma_gemm<<<dim3(P_PIX / 128, NQKV / 128, 2), 256, gemm_smem>>>(wqh, wql, xth, xtl, qkv, NQKV);
    // 2a) depthwise for q,k channels (0..767)
    dwconv_kernel<<<(2 * 768 * 2048) / 256, 256>>>(qkv, w_dw, dwb, 0, 768);
    // fork: cattn + chan_coef on side stream, overlapped with dwconv_v
    cudaEventRecord(evFork, 0);
    cudaStreamWaitEvent(s2, evFork, 0);
    cattn_kernel<<<dim3(CSPLIT, 16), 256, 0, s2>>>(dwb, cpart, cnp);
    chan_coef_kernel<<<96, 256, 0, s2>>>(cpart, cnp, temp, a1, a2, a3, a4, ccoef);
    cudaEventRecord(evJoin, s2);
    // 2b) depthwise for v channels (768..1151) on main stream
    dwconv_kernel<<<(2 * 384 * 2048) / 256, 256>>>(qkv, w_dw, dwb, 768, 384);
    cudaStreamWaitEvent(0, evJoin, 0);
    // 3) fused spatial + channel output, emits proj input bf16 hi/lo transposed
    spatial_kernel<<<dim3(512, HEADS), 256, spatial_smem>>>(
        dwb, ccoef, temp, a1, a2, a3, a4, xth, xtl);
    // 4) proj GEMM (M=384) -> d_out
    hmma_gemm<<<dim3(P_PIX / 128, NCH / 128, 2), 256, gemm_smem>>>(wph, wpl, xth, xtl, out, NCH);
}